// round 1
// baseline (speedup 1.0000x reference)
#include <cuda_runtime.h>
#include <cuda_bf16.h>
#include <cstddef>

// Problem constants
#define BB 2
#define SS 2048
#define DD 1024
#define HH 16
#define HD 64
#define MM (BB*SS)   // 4096

// Scratch buffers (device globals; no allocation allowed)
__device__ float g_Q[MM * DD];
__device__ float g_K[MM * DD];
__device__ float g_V[MM * DD];
__device__ float g_Yb[MM * DD];

// ---------------------------------------------------------------------------
// SGEMM: C[M,N] = A[M,K] @ W[N,K]^T + bias[N]
// Tiles: 128x128x16, 256 threads, 8x8 per-thread micro-tile.
// ---------------------------------------------------------------------------
__global__ void __launch_bounds__(256) sgemm_bias(
    const float* __restrict__ A,
    const float* __restrict__ W,
    const float* __restrict__ bias,
    float* __restrict__ C,
    int M, int N, int K)
{
    __shared__ float As[16][128 + 4];
    __shared__ float Bs[16][128 + 4];

    const int tid  = threadIdx.x;
    const int brow = blockIdx.y * 128;
    const int bcol = blockIdx.x * 128;
    const int tx   = tid & 15;
    const int ty   = tid >> 4;
    const int lrow = tid >> 2;          // 0..63
    const int lk   = (tid & 3) << 2;    // 0,4,8,12

    float acc[8][8];
#pragma unroll
    for (int i = 0; i < 8; ++i)
#pragma unroll
        for (int j = 0; j < 8; ++j)
            acc[i][j] = 0.0f;

    for (int k0 = 0; k0 < K; k0 += 16) {
#pragma unroll
        for (int p = 0; p < 2; ++p) {
            int r = lrow + p * 64;
            float4 av = *reinterpret_cast<const float4*>(
                &A[(size_t)(brow + r) * K + k0 + lk]);
            As[lk + 0][r] = av.x;
            As[lk + 1][r] = av.y;
            As[lk + 2][r] = av.z;
            As[lk + 3][r] = av.w;
            float4 wv = *reinterpret_cast<const float4*>(
                &W[(size_t)(bcol + r) * K + k0 + lk]);
            Bs[lk + 0][r] = wv.x;
            Bs[lk + 1][r] = wv.y;
            Bs[lk + 2][r] = wv.z;
            Bs[lk + 3][r] = wv.w;
        }
        __syncthreads();

#pragma unroll
        for (int kk = 0; kk < 16; ++kk) {
            float a[8], b[8];
            *reinterpret_cast<float4*>(&a[0]) =
                *reinterpret_cast<const float4*>(&As[kk][ty * 8]);
            *reinterpret_cast<float4*>(&a[4]) =
                *reinterpret_cast<const float4*>(&As[kk][ty * 8 + 4]);
            *reinterpret_cast<float4*>(&b[0]) =
                *reinterpret_cast<const float4*>(&Bs[kk][tx * 8]);
            *reinterpret_cast<float4*>(&b[4]) =
                *reinterpret_cast<const float4*>(&Bs[kk][tx * 8 + 4]);
#pragma unroll
            for (int i = 0; i < 8; ++i)
#pragma unroll
                for (int j = 0; j < 8; ++j)
                    acc[i][j] = fmaf(a[i], b[j], acc[i][j]);
        }
        __syncthreads();
    }

#pragma unroll
    for (int i = 0; i < 8; ++i) {
        int r = brow + ty * 8 + i;
#pragma unroll
        for (int j = 0; j < 8; j += 4) {
            int c = bcol + tx * 8 + j;
            float4 o;
            o.x = acc[i][j + 0] + bias[c + 0];
            o.y = acc[i][j + 1] + bias[c + 1];
            o.z = acc[i][j + 2] + bias[c + 2];
            o.w = acc[i][j + 3] + bias[c + 3];
            *reinterpret_cast<float4*>(&C[(size_t)r * N + c]) = o;
        }
    }
}

// ---------------------------------------------------------------------------
// Flash attention (causal), fp32.
// Grid: (S/64, H, B). Block: 64 threads, one q-row per thread.
// Q/K/V/Y layout: [B, S, D] with head h occupying columns [h*64, h*64+64).
// ---------------------------------------------------------------------------
__global__ void __launch_bounds__(64) attn_kernel(
    const float* __restrict__ Q,
    const float* __restrict__ K,
    const float* __restrict__ V,
    float* __restrict__ Y)
{
    const int b  = blockIdx.z;
    const int h  = blockIdx.y;
    const int qt = blockIdx.x;
    const int tid = threadIdx.x;
    const int row = qt * 64 + tid;

    __shared__ float ks[64][HD];
    __shared__ float vs[64][HD];

    // Load q row, pre-scaled by 1/sqrt(D) = 1/32
    float q[HD];
    {
        const float* qp = Q + ((size_t)(b * SS + row)) * DD + h * HD;
        const float scale = 0.03125f;
#pragma unroll
        for (int t = 0; t < 16; ++t) {
            float4 v4 = *reinterpret_cast<const float4*>(qp + 4 * t);
            q[4 * t + 0] = v4.x * scale;
            q[4 * t + 1] = v4.y * scale;
            q[4 * t + 2] = v4.z * scale;
            q[4 * t + 3] = v4.w * scale;
        }
    }

    float m = -1e30f;
    float l = 0.0f;
    float acc[HD];
#pragma unroll
    for (int d = 0; d < HD; ++d) acc[d] = 0.0f;

    for (int kt = 0; kt <= qt; ++kt) {
        __syncthreads();   // previous tile fully consumed
        // Cooperative load of K/V tile: 64 rows x 16 float4
#pragma unroll
        for (int i = 0; i < 16; ++i) {
            int c  = tid + i * 64;
            int r  = c >> 4;
            int d4 = (c & 15) * 4;
            size_t off = ((size_t)(b * SS + kt * 64 + r)) * DD + h * HD + d4;
            *reinterpret_cast<float4*>(&ks[r][d4]) =
                *reinterpret_cast<const float4*>(K + off);
            *reinterpret_cast<float4*>(&vs[r][d4]) =
                *reinterpret_cast<const float4*>(V + off);
        }
        __syncthreads();

        const int kbase = kt * 64;
#pragma unroll 1
        for (int sub = 0; sub < 4; ++sub) {
            float s[16];
#pragma unroll
            for (int jj = 0; jj < 16; ++jj) {
                int j = sub * 16 + jj;
                const float4* kr = reinterpret_cast<const float4*>(&ks[j][0]);
                float s0 = 0.f, s1 = 0.f, s2 = 0.f, s3 = 0.f;
#pragma unroll
                for (int t = 0; t < 16; ++t) {
                    float4 kv = kr[t];
                    s0 = fmaf(q[4 * t + 0], kv.x, s0);
                    s1 = fmaf(q[4 * t + 1], kv.y, s1);
                    s2 = fmaf(q[4 * t + 2], kv.z, s2);
                    s3 = fmaf(q[4 * t + 3], kv.w, s3);
                }
                float sv = (s0 + s1) + (s2 + s3);
                s[jj] = (kbase + j <= row) ? sv : -1e30f;
            }

            float mt = s[0];
#pragma unroll
            for (int jj = 1; jj < 16; ++jj) mt = fmaxf(mt, s[jj]);
            float m_new = fmaxf(m, mt);
            float corr = __expf(m - m_new);   // ==1 when max unchanged
            l *= corr;
#pragma unroll
            for (int d = 0; d < HD; ++d) acc[d] *= corr;
            m = m_new;

#pragma unroll
            for (int jj = 0; jj < 16; ++jj) {
                float p = __expf(s[jj] - m);
                l += p;
                const float4* vr =
                    reinterpret_cast<const float4*>(&vs[sub * 16 + jj][0]);
#pragma unroll
                for (int t = 0; t < 16; ++t) {
                    float4 vv = vr[t];
                    acc[4 * t + 0] = fmaf(p, vv.x, acc[4 * t + 0]);
                    acc[4 * t + 1] = fmaf(p, vv.y, acc[4 * t + 1]);
                    acc[4 * t + 2] = fmaf(p, vv.z, acc[4 * t + 2]);
                    acc[4 * t + 3] = fmaf(p, vv.w, acc[4 * t + 3]);
                }
            }
        }
    }

    const float inv = 1.0f / l;
    float* yp = Y + ((size_t)(b * SS + row)) * DD + h * HD;
#pragma unroll
    for (int t = 0; t < 16; ++t) {
        float4 o;
        o.x = acc[4 * t + 0] * inv;
        o.y = acc[4 * t + 1] * inv;
        o.z = acc[4 * t + 2] * inv;
        o.w = acc[4 * t + 3] * inv;
        *reinterpret_cast<float4*>(yp + 4 * t) = o;
    }
}

// ---------------------------------------------------------------------------
// Launch
// ---------------------------------------------------------------------------
extern "C" void kernel_launch(void* const* d_in, const int* in_sizes, int n_in,
                              void* d_out, int out_size)
{
    (void)in_sizes; (void)n_in; (void)out_size;
    const float* x  = (const float*)d_in[0];
    const float* Wq = (const float*)d_in[1];
    const float* bq = (const float*)d_in[2];
    const float* Wk = (const float*)d_in[3];
    const float* bk = (const float*)d_in[4];
    const float* Wv = (const float*)d_in[5];
    const float* bv = (const float*)d_in[6];
    const float* Wp = (const float*)d_in[7];
    const float* bp = (const float*)d_in[8];
    float* out = (float*)d_out;

    float *Qb, *Kb, *Vb, *Yb;
    cudaGetSymbolAddress((void**)&Qb, g_Q);
    cudaGetSymbolAddress((void**)&Kb, g_K);
    cudaGetSymbolAddress((void**)&Vb, g_V);
    cudaGetSymbolAddress((void**)&Yb, g_Yb);

    dim3 gg(DD / 128, MM / 128);   // (8, 32)
    sgemm_bias<<<gg, 256>>>(x, Wq, bq, Qb, MM, DD, DD);
    sgemm_bias<<<gg, 256>>>(x, Wk, bk, Kb, MM, DD, DD);
    sgemm_bias<<<gg, 256>>>(x, Wv, bv, Vb, MM, DD, DD);

    attn_kernel<<<dim3(SS / 64, HH, BB), 64>>>(Qb, Kb, Vb, Yb);

    sgemm_bias<<<gg, 256>>>(Yb, Wp, bp, out, MM, DD, DD);
}

// round 3
// speedup vs baseline: 1.1074x; 1.1074x over previous
#include <cuda_runtime.h>
#include <cuda_bf16.h>
#include <cstdint>
#include <cstddef>

// Problem constants
#define BB 2
#define SS 2048
#define DD 1024
#define HH 16
#define HD 64
#define MM (BB*SS)   // 4096

// Scratch buffers (device globals; no allocation allowed)
__device__ float g_Q[MM * DD];
__device__ float g_K[MM * DD];
__device__ float g_V[MM * DD];
__device__ float g_Yb[MM * DD];
__device__ __nv_bfloat16 g_Ahi[MM * DD];
__device__ __nv_bfloat16 g_Alo[MM * DD];
__device__ __nv_bfloat16 g_Whi[DD * DD];
__device__ __nv_bfloat16 g_Wlo[DD * DD];

// ---------------------------------------------------------------------------
// Helpers
// ---------------------------------------------------------------------------
__device__ __forceinline__ uint32_t smem_u32(const void* p) {
    uint32_t a;
    asm("{ .reg .u64 t; cvta.to.shared.u64 t, %1; cvt.u32.u64 %0, t; }"
        : "=r"(a) : "l"(p));
    return a;
}

#define SWZ(off) ((uint32_t)(off) ^ ((((uint32_t)(off)) >> 3) & 0x70))

__device__ __forceinline__ void cp_async16(uint32_t dst, const void* src) {
    asm volatile("cp.async.cg.shared.global [%0], [%1], 16;"
                 :: "r"(dst), "l"(src) : "memory");
}
__device__ __forceinline__ void cp_commit() {
    asm volatile("cp.async.commit_group;" ::: "memory");
}
template <int N>
__device__ __forceinline__ void cp_wait() {
    asm volatile("cp.async.wait_group %0;" :: "n"(N) : "memory");
}

__device__ __forceinline__ void ldsm_x4(uint32_t* r, uint32_t addr) {
    asm volatile("ldmatrix.sync.aligned.m8n8.x4.shared.b16 {%0,%1,%2,%3}, [%4];"
                 : "=r"(r[0]), "=r"(r[1]), "=r"(r[2]), "=r"(r[3])
                 : "r"(addr));
}

__device__ __forceinline__ void mma16816(float* d, const uint32_t* a,
                                         const uint32_t* b) {
    asm volatile(
        "mma.sync.aligned.m16n8k16.row.col.f32.bf16.bf16.f32 "
        "{%0,%1,%2,%3}, {%4,%5,%6,%7}, {%8,%9}, {%0,%1,%2,%3};"
        : "+f"(d[0]), "+f"(d[1]), "+f"(d[2]), "+f"(d[3])
        : "r"(a[0]), "r"(a[1]), "r"(a[2]), "r"(a[3]), "r"(b[0]), "r"(b[1]));
}

// ---------------------------------------------------------------------------
// Split fp32 -> bf16 hi + bf16 lo (residual). n4 = element count / 4.
// ---------------------------------------------------------------------------
__global__ void __launch_bounds__(256) split_kernel(
    const float4* __restrict__ src,
    uint2* __restrict__ hi,
    uint2* __restrict__ lo,
    int n4)
{
    int i = blockIdx.x * blockDim.x + threadIdx.x;
    if (i >= n4) return;
    float4 v = src[i];
    __nv_bfloat162 h0 = __float22bfloat162_rn(make_float2(v.x, v.y));
    __nv_bfloat162 h1 = __float22bfloat162_rn(make_float2(v.z, v.w));
    float2 hf0 = __bfloat1622float2(h0);
    float2 hf1 = __bfloat1622float2(h1);
    __nv_bfloat162 l0 = __float22bfloat162_rn(make_float2(v.x - hf0.x, v.y - hf0.y));
    __nv_bfloat162 l1 = __float22bfloat162_rn(make_float2(v.z - hf1.x, v.w - hf1.y));
    uint2 ho, loo;
    ho.x = *reinterpret_cast<uint32_t*>(&h0);
    ho.y = *reinterpret_cast<uint32_t*>(&h1);
    loo.x = *reinterpret_cast<uint32_t*>(&l0);
    loo.y = *reinterpret_cast<uint32_t*>(&l1);
    hi[i] = ho;
    lo[i] = loo;
}

// ---------------------------------------------------------------------------
// mma.sync bf16 GEMM with 2-term split: C = A @ W^T + bias
// C[4096,1024], A/W pre-split into hi/lo bf16.
// CTA tile 128x128, 8 warps (2m x 4n), warp tile 64x32, K-chunk 64,
// cp.async double-buffered SW128 smem.
// Stage layout: Ahi[128][64]bf16 (16KB) | Alo | Bhi | Blo  = 64KB/stage.
// ---------------------------------------------------------------------------
#define ST_BYTES 65536
#define GEMM_SMEM (2 * ST_BYTES)

__global__ void __launch_bounds__(256) gemm_mma_bias(
    const __nv_bfloat16* __restrict__ Ahi,
    const __nv_bfloat16* __restrict__ Alo,
    const __nv_bfloat16* __restrict__ Whi,
    const __nv_bfloat16* __restrict__ Wlo,
    const float* __restrict__ bias,
    float* __restrict__ C)
{
    extern __shared__ char smem[];
    const uint32_t sbase = smem_u32(smem);

    const int tid  = threadIdx.x;
    const int lane = tid & 31;
    const int warp = tid >> 5;
    const int wm   = warp >> 2;        // 0..1
    const int wn   = warp & 3;         // 0..3
    const int brow = blockIdx.y * 128;
    const int bcol = blockIdx.x * 128;

    // --- cp.async load indexing (per thread: 4 chunks per 16KB tile) ---
    // chunk idx = tid + i*256 -> row = idx>>3, c = idx&7 (16B chunks)
    const int ldr = tid >> 3;          // base row (for i=0); rows step 32 per i
    const int ldc = tid & 7;
    uint32_t ldswz[4];
#pragma unroll
    for (int i = 0; i < 4; ++i)
        ldswz[i] = SWZ((ldr + i * 32) * 128 + ldc * 16);

    auto issue_stage = [&](int kt, int buf) {
        const uint32_t st = sbase + buf * ST_BYTES;
        const int k0 = kt * 64;
#pragma unroll
        for (int i = 0; i < 4; ++i) {
            int r = ldr + i * 32;
            size_t offA = (size_t)(brow + r) * DD + k0 + ldc * 8;
            size_t offB = (size_t)(bcol + r) * DD + k0 + ldc * 8;
            cp_async16(st + 0     + ldswz[i], Ahi + offA);
            cp_async16(st + 16384 + ldswz[i], Alo + offA);
            cp_async16(st + 32768 + ldswz[i], Whi + offB);
            cp_async16(st + 49152 + ldswz[i], Wlo + offB);
        }
        cp_commit();
    };

    // --- ldmatrix address components ---
    // A: lanes 0-15 -> rows 0-15 chunk0; lanes 16-31 -> rows 0-15 chunk+16
    const uint32_t aRowPart = (uint32_t)(lane & 15) * 128 + ((lane >> 4) << 4);
    // B: lanes grouped (n0-7,c0)(n0-7,c16)(n8-15,c0)(n8-15,c16)
    const uint32_t bRowPart =
        (uint32_t)((lane & 7) + ((lane >> 4) << 3)) * 128 + (((lane >> 3) & 1) << 4);
    uint32_t aswz[4], bswz[4];
#pragma unroll
    for (int kf = 0; kf < 4; ++kf) {
        aswz[kf] = SWZ(aRowPart + kf * 32);
        bswz[kf] = SWZ(bRowPart + kf * 32);
    }
    const uint32_t aWarpOff = wm * 8192;   // wm*64 rows * 128B
    const uint32_t bWarpOff = wn * 4096;   // wn*32 rows * 128B

    float acc[4][4][4];
#pragma unroll
    for (int i = 0; i < 4; ++i)
#pragma unroll
        for (int j = 0; j < 4; ++j)
#pragma unroll
            for (int t = 0; t < 4; ++t)
                acc[i][j][t] = 0.0f;

    issue_stage(0, 0);

    for (int kt = 0; kt < 16; ++kt) {
        const int buf = kt & 1;
        if (kt < 15) {
            issue_stage(kt + 1, buf ^ 1);
            cp_wait<1>();
        } else {
            cp_wait<0>();
        }
        __syncthreads();

        const uint32_t st = sbase + buf * ST_BYTES;
#pragma unroll
        for (int kf = 0; kf < 4; ++kf) {
            uint32_t ah[4][4], al[4][4], bh[4][2], bl[4][2];
#pragma unroll
            for (int mf = 0; mf < 4; ++mf) {
                uint32_t base = st + aWarpOff + mf * 2048 + aswz[kf];
                ldsm_x4(ah[mf], base);
                ldsm_x4(al[mf], base + 16384);
            }
#pragma unroll
            for (int nf2 = 0; nf2 < 2; ++nf2) {
                uint32_t tmp[4];
                uint32_t base = st + 32768 + bWarpOff + nf2 * 2048 + bswz[kf];
                ldsm_x4(tmp, base);
                bh[2 * nf2 + 0][0] = tmp[0]; bh[2 * nf2 + 0][1] = tmp[1];
                bh[2 * nf2 + 1][0] = tmp[2]; bh[2 * nf2 + 1][1] = tmp[3];
                ldsm_x4(tmp, base + 16384);
                bl[2 * nf2 + 0][0] = tmp[0]; bl[2 * nf2 + 0][1] = tmp[1];
                bl[2 * nf2 + 1][0] = tmp[2]; bl[2 * nf2 + 1][1] = tmp[3];
            }
#pragma unroll
            for (int mf = 0; mf < 4; ++mf)
#pragma unroll
                for (int nf = 0; nf < 4; ++nf) {
                    mma16816(acc[mf][nf], ah[mf], bh[nf]);
                    mma16816(acc[mf][nf], ah[mf], bl[nf]);
                    mma16816(acc[mf][nf], al[mf], bh[nf]);
                }
        }
        __syncthreads();
    }

    // Epilogue
    const int r0 = brow + wm * 64 + (lane >> 2);
    const int c0 = bcol + wn * 32 + 2 * (lane & 3);
#pragma unroll
    for (int mf = 0; mf < 4; ++mf) {
#pragma unroll
        for (int nf = 0; nf < 4; ++nf) {
            int col = c0 + nf * 8;
            float b0 = bias[col], b1 = bias[col + 1];
            int ra = r0 + mf * 16;
            float2 o0 = make_float2(acc[mf][nf][0] + b0, acc[mf][nf][1] + b1);
            float2 o1 = make_float2(acc[mf][nf][2] + b0, acc[mf][nf][3] + b1);
            *reinterpret_cast<float2*>(&C[(size_t)ra * DD + col]) = o0;
            *reinterpret_cast<float2*>(&C[(size_t)(ra + 8) * DD + col]) = o1;
        }
    }
}

// ---------------------------------------------------------------------------
// Flash attention (causal), fp32, 2 threads per q-row.
// Grid: (S/64, H, B). Block: 128 threads -> 64 q rows.
// ---------------------------------------------------------------------------
__global__ void __launch_bounds__(128) attn_kernel(
    const float* __restrict__ Q,
    const float* __restrict__ K,
    const float* __restrict__ V,
    float* __restrict__ Y)
{
    const int b    = blockIdx.z;
    const int h    = blockIdx.y;
    const int qt   = blockIdx.x;
    const int tid  = threadIdx.x;
    const int rowl = tid >> 1;
    const int half = tid & 1;
    const int row  = qt * 64 + rowl;

    __shared__ float ks[64][HD];
    __shared__ float vs[64][HD];

    float q[32];
    {
        const float* qp = Q + ((size_t)(b * SS + row)) * DD + h * HD + half * 32;
        const float scale = 0.03125f;   // 1/sqrt(1024)
#pragma unroll
        for (int t = 0; t < 8; ++t) {
            float4 v4 = *reinterpret_cast<const float4*>(qp + 4 * t);
            q[4 * t + 0] = v4.x * scale;
            q[4 * t + 1] = v4.y * scale;
            q[4 * t + 2] = v4.z * scale;
            q[4 * t + 3] = v4.w * scale;
        }
    }

    float m = -1e30f;
    float l = 0.0f;
    float acc[32];
#pragma unroll
    for (int d = 0; d < 32; ++d) acc[d] = 0.0f;

    for (int kt = 0; kt <= qt; ++kt) {
        __syncthreads();
#pragma unroll
        for (int i = 0; i < 8; ++i) {
            int c  = tid + i * 128;
            int r  = c >> 4;
            int d4 = (c & 15) * 4;
            size_t off = ((size_t)(b * SS + kt * 64 + r)) * DD + h * HD + d4;
            *reinterpret_cast<float4*>(&ks[r][d4]) =
                *reinterpret_cast<const float4*>(K + off);
            *reinterpret_cast<float4*>(&vs[r][d4]) =
                *reinterpret_cast<const float4*>(V + off);
        }
        __syncthreads();

        const int kbase = kt * 64;
#pragma unroll 1
        for (int sub = 0; sub < 4; ++sub) {
            float s[16];
#pragma unroll
            for (int jj = 0; jj < 16; ++jj) {
                int j = sub * 16 + jj;
                const float4* kr =
                    reinterpret_cast<const float4*>(&ks[j][half * 32]);
                float s0 = 0.f, s1 = 0.f, s2 = 0.f, s3 = 0.f;
#pragma unroll
                for (int t = 0; t < 8; ++t) {
                    float4 kv = kr[t];
                    s0 = fmaf(q[4 * t + 0], kv.x, s0);
                    s1 = fmaf(q[4 * t + 1], kv.y, s1);
                    s2 = fmaf(q[4 * t + 2], kv.z, s2);
                    s3 = fmaf(q[4 * t + 3], kv.w, s3);
                }
                float sv = (s0 + s1) + (s2 + s3);
                sv += __shfl_xor_sync(0xffffffffu, sv, 1);
                s[jj] = (kbase + j <= row) ? sv : -1e30f;
            }

            float mt = s[0];
#pragma unroll
            for (int jj = 1; jj < 16; ++jj) mt = fmaxf(mt, s[jj]);
            float m_new = fmaxf(m, mt);
            float corr = __expf(m - m_new);
            l *= corr;
#pragma unroll
            for (int d = 0; d < 32; ++d) acc[d] *= corr;
            m = m_new;

#pragma unroll
            for (int jj = 0; jj < 16; ++jj) {
                float p = __expf(s[jj] - m);
                l += p;
                const float4* vr = reinterpret_cast<const float4*>(
                    &vs[sub * 16 + jj][half * 32]);
#pragma unroll
                for (int t = 0; t < 8; ++t) {
                    float4 vv = vr[t];
                    acc[4 * t + 0] = fmaf(p, vv.x, acc[4 * t + 0]);
                    acc[4 * t + 1] = fmaf(p, vv.y, acc[4 * t + 1]);
                    acc[4 * t + 2] = fmaf(p, vv.z, acc[4 * t + 2]);
                    acc[4 * t + 3] = fmaf(p, vv.w, acc[4 * t + 3]);
                }
            }
        }
    }

    const float inv = 1.0f / l;
    float* yp = Y + ((size_t)(b * SS + row)) * DD + h * HD + half * 32;
#pragma unroll
    for (int t = 0; t < 8; ++t) {
        float4 o;
        o.x = acc[4 * t + 0] * inv;
        o.y = acc[4 * t + 1] * inv;
        o.z = acc[4 * t + 2] * inv;
        o.w = acc[4 * t + 3] * inv;
        *reinterpret_cast<float4*>(yp + 4 * t) = o;
    }
}

// ---------------------------------------------------------------------------
// Launch
// ---------------------------------------------------------------------------
extern "C" void kernel_launch(void* const* d_in, const int* in_sizes, int n_in,
                              void* d_out, int out_size)
{
    (void)in_sizes; (void)n_in; (void)out_size;
    const float* x  = (const float*)d_in[0];
    const float* Wq = (const float*)d_in[1];
    const float* bq = (const float*)d_in[2];
    const float* Wk = (const float*)d_in[3];
    const float* bk = (const float*)d_in[4];
    const float* Wv = (const float*)d_in[5];
    const float* bv = (const float*)d_in[6];
    const float* Wp = (const float*)d_in[7];
    const float* bp = (const float*)d_in[8];
    float* out = (float*)d_out;

    float *Qb, *Kb, *Vb, *Yb;
    __nv_bfloat16 *Ahi, *Alo, *Whi, *Wlo;
    cudaGetSymbolAddress((void**)&Qb, g_Q);
    cudaGetSymbolAddress((void**)&Kb, g_K);
    cudaGetSymbolAddress((void**)&Vb, g_V);
    cudaGetSymbolAddress((void**)&Yb, g_Yb);
    cudaGetSymbolAddress((void**)&Ahi, g_Ahi);
    cudaGetSymbolAddress((void**)&Alo, g_Alo);
    cudaGetSymbolAddress((void**)&Whi, g_Whi);
    cudaGetSymbolAddress((void**)&Wlo, g_Wlo);

    cudaFuncSetAttribute(gemm_mma_bias,
                         cudaFuncAttributeMaxDynamicSharedMemorySize, GEMM_SMEM);

    const int nX4 = MM * DD / 4;   // 1M float4
    const int nW4 = DD * DD / 4;   // 256K float4
    dim3 gg(DD / 128, MM / 128);   // (8, 32)

    split_kernel<<<(nX4 + 255) / 256, 256>>>(
        (const float4*)x, (uint2*)Ahi, (uint2*)Alo, nX4);

    split_kernel<<<(nW4 + 255) / 256, 256>>>(
        (const float4*)Wq, (uint2*)Whi, (uint2*)Wlo, nW4);
    gemm_mma_bias<<<gg, 256, GEMM_SMEM>>>(Ahi, Alo, Whi, Wlo, bq, Qb);

    split_kernel<<<(nW4 + 255) / 256, 256>>>(
        (const float4*)Wk, (uint2*)Whi, (uint2*)Wlo, nW4);
    gemm_mma_bias<<<gg, 256, GEMM_SMEM>>>(Ahi, Alo, Whi, Wlo, bk, Kb);

    split_kernel<<<(nW4 + 255) / 256, 256>>>(
        (const float4*)Wv, (uint2*)Whi, (uint2*)Wlo, nW4);
    gemm_mma_bias<<<gg, 256, GEMM_SMEM>>>(Ahi, Alo, Whi, Wlo, bv, Vb);

    attn_kernel<<<dim3(SS / 64, HH, BB), 128>>>(Qb, Kb, Vb, Yb);

    split_kernel<<<(nX4 + 255) / 256, 256>>>(
        (const float4*)Yb, (uint2*)Ahi, (uint2*)Alo, nX4);
    split_kernel<<<(nW4 + 255) / 256, 256>>>(
        (const float4*)Wp, (uint2*)Whi, (uint2*)Wlo, nW4);
    gemm_mma_bias<<<gg, 256, GEMM_SMEM>>>(Ahi, Alo, Whi, Wlo, bp, out);
}

// round 4
// speedup vs baseline: 3.7284x; 3.3667x over previous
#include <cuda_runtime.h>
#include <cuda_bf16.h>
#include <cuda_fp16.h>
#include <cstdint>
#include <cstddef>

// Problem constants
#define BB 2
#define SS 2048
#define DD 1024
#define HH 16
#define HD 64
#define MM (BB*SS)   // 4096

// Scratch buffers (device globals; no allocation allowed)
__device__ float g_Q[MM * DD];
__device__ float g_K[MM * DD];
__device__ float g_V[MM * DD];
__device__ float g_Yb[MM * DD];
__device__ __nv_bfloat16 g_Ahi[MM * DD];
__device__ __nv_bfloat16 g_Alo[MM * DD];
__device__ __nv_bfloat16 g_Whi[DD * DD];
__device__ __nv_bfloat16 g_Wlo[DD * DD];

// ---------------------------------------------------------------------------
// Helpers
// ---------------------------------------------------------------------------
__device__ __forceinline__ uint32_t smem_u32(const void* p) {
    uint32_t a;
    asm("{ .reg .u64 t; cvta.to.shared.u64 t, %1; cvt.u32.u64 %0, t; }"
        : "=r"(a) : "l"(p));
    return a;
}

#define SWZ(off) ((uint32_t)(off) ^ ((((uint32_t)(off)) >> 3) & 0x70))

__device__ __forceinline__ void cp_async16(uint32_t dst, const void* src) {
    asm volatile("cp.async.cg.shared.global [%0], [%1], 16;"
                 :: "r"(dst), "l"(src) : "memory");
}
__device__ __forceinline__ void cp_commit() {
    asm volatile("cp.async.commit_group;" ::: "memory");
}
template <int N>
__device__ __forceinline__ void cp_wait() {
    asm volatile("cp.async.wait_group %0;" :: "n"(N) : "memory");
}

__device__ __forceinline__ void ldsm_x4(uint32_t* r, uint32_t addr) {
    asm volatile("ldmatrix.sync.aligned.m8n8.x4.shared.b16 {%0,%1,%2,%3}, [%4];"
                 : "=r"(r[0]), "=r"(r[1]), "=r"(r[2]), "=r"(r[3])
                 : "r"(addr));
}

__device__ __forceinline__ void mma16816(float* d, const uint32_t* a,
                                         const uint32_t* b) {
    asm volatile(
        "mma.sync.aligned.m16n8k16.row.col.f32.bf16.bf16.f32 "
        "{%0,%1,%2,%3}, {%4,%5,%6,%7}, {%8,%9}, {%0,%1,%2,%3};"
        : "+f"(d[0]), "+f"(d[1]), "+f"(d[2]), "+f"(d[3])
        : "r"(a[0]), "r"(a[1]), "r"(a[2]), "r"(a[3]), "r"(b[0]), "r"(b[1]));
}

__device__ __forceinline__ void mma16816h(float* d, const uint32_t* a,
                                          uint32_t b0, uint32_t b1) {
    asm volatile(
        "mma.sync.aligned.m16n8k16.row.col.f32.f16.f16.f32 "
        "{%0,%1,%2,%3}, {%4,%5,%6,%7}, {%8,%9}, {%0,%1,%2,%3};"
        : "+f"(d[0]), "+f"(d[1]), "+f"(d[2]), "+f"(d[3])
        : "r"(a[0]), "r"(a[1]), "r"(a[2]), "r"(a[3]), "r"(b0), "r"(b1));
}

__device__ __forceinline__ float ex2(float x) {
    float y;
    asm("ex2.approx.ftz.f32 %0, %1;" : "=f"(y) : "f"(x));
    return y;
}

__device__ __forceinline__ uint32_t packh2(float a, float b) {
    __half2 h = __floats2half2_rn(a, b);
    return *reinterpret_cast<uint32_t*>(&h);
}

// ---------------------------------------------------------------------------
// Split fp32 -> bf16 hi + bf16 lo (residual). n4 = element count / 4.
// ---------------------------------------------------------------------------
__global__ void __launch_bounds__(256) split_kernel(
    const float4* __restrict__ src,
    uint2* __restrict__ hi,
    uint2* __restrict__ lo,
    int n4)
{
    int i = blockIdx.x * blockDim.x + threadIdx.x;
    if (i >= n4) return;
    float4 v = src[i];
    __nv_bfloat162 h0 = __float22bfloat162_rn(make_float2(v.x, v.y));
    __nv_bfloat162 h1 = __float22bfloat162_rn(make_float2(v.z, v.w));
    float2 hf0 = __bfloat1622float2(h0);
    float2 hf1 = __bfloat1622float2(h1);
    __nv_bfloat162 l0 = __float22bfloat162_rn(make_float2(v.x - hf0.x, v.y - hf0.y));
    __nv_bfloat162 l1 = __float22bfloat162_rn(make_float2(v.z - hf1.x, v.w - hf1.y));
    uint2 ho, loo;
    ho.x = *reinterpret_cast<uint32_t*>(&h0);
    ho.y = *reinterpret_cast<uint32_t*>(&h1);
    loo.x = *reinterpret_cast<uint32_t*>(&l0);
    loo.y = *reinterpret_cast<uint32_t*>(&l1);
    hi[i] = ho;
    lo[i] = loo;
}

// ---------------------------------------------------------------------------
// mma.sync bf16 GEMM with 2-term split: C = A @ W^T + bias  (unchanged, proven)
// ---------------------------------------------------------------------------
#define ST_BYTES 65536
#define GEMM_SMEM (2 * ST_BYTES)

__global__ void __launch_bounds__(256) gemm_mma_bias(
    const __nv_bfloat16* __restrict__ Ahi,
    const __nv_bfloat16* __restrict__ Alo,
    const __nv_bfloat16* __restrict__ Whi,
    const __nv_bfloat16* __restrict__ Wlo,
    const float* __restrict__ bias,
    float* __restrict__ C)
{
    extern __shared__ char smem[];
    const uint32_t sbase = smem_u32(smem);

    const int tid  = threadIdx.x;
    const int lane = tid & 31;
    const int warp = tid >> 5;
    const int wm   = warp >> 2;
    const int wn   = warp & 3;
    const int brow = blockIdx.y * 128;
    const int bcol = blockIdx.x * 128;

    const int ldr = tid >> 3;
    const int ldc = tid & 7;
    uint32_t ldswz[4];
#pragma unroll
    for (int i = 0; i < 4; ++i)
        ldswz[i] = SWZ((ldr + i * 32) * 128 + ldc * 16);

    auto issue_stage = [&](int kt, int buf) {
        const uint32_t st = sbase + buf * ST_BYTES;
        const int k0 = kt * 64;
#pragma unroll
        for (int i = 0; i < 4; ++i) {
            int r = ldr + i * 32;
            size_t offA = (size_t)(brow + r) * DD + k0 + ldc * 8;
            size_t offB = (size_t)(bcol + r) * DD + k0 + ldc * 8;
            cp_async16(st + 0     + ldswz[i], Ahi + offA);
            cp_async16(st + 16384 + ldswz[i], Alo + offA);
            cp_async16(st + 32768 + ldswz[i], Whi + offB);
            cp_async16(st + 49152 + ldswz[i], Wlo + offB);
        }
        cp_commit();
    };

    const uint32_t aRowPart = (uint32_t)(lane & 15) * 128 + ((lane >> 4) << 4);
    const uint32_t bRowPart =
        (uint32_t)((lane & 7) + ((lane >> 4) << 3)) * 128 + (((lane >> 3) & 1) << 4);
    uint32_t aswz[4], bswz[4];
#pragma unroll
    for (int kf = 0; kf < 4; ++kf) {
        aswz[kf] = SWZ(aRowPart + kf * 32);
        bswz[kf] = SWZ(bRowPart + kf * 32);
    }
    const uint32_t aWarpOff = wm * 8192;
    const uint32_t bWarpOff = wn * 4096;

    float acc[4][4][4];
#pragma unroll
    for (int i = 0; i < 4; ++i)
#pragma unroll
        for (int j = 0; j < 4; ++j)
#pragma unroll
            for (int t = 0; t < 4; ++t)
                acc[i][j][t] = 0.0f;

    issue_stage(0, 0);

    for (int kt = 0; kt < 16; ++kt) {
        const int buf = kt & 1;
        if (kt < 15) {
            issue_stage(kt + 1, buf ^ 1);
            cp_wait<1>();
        } else {
            cp_wait<0>();
        }
        __syncthreads();

        const uint32_t st = sbase + buf * ST_BYTES;
#pragma unroll
        for (int kf = 0; kf < 4; ++kf) {
            uint32_t ah[4][4], al[4][4], bh[4][2], bl[4][2];
#pragma unroll
            for (int mf = 0; mf < 4; ++mf) {
                uint32_t base = st + aWarpOff + mf * 2048 + aswz[kf];
                ldsm_x4(ah[mf], base);
                ldsm_x4(al[mf], base + 16384);
            }
#pragma unroll
            for (int nf2 = 0; nf2 < 2; ++nf2) {
                uint32_t tmp[4];
                uint32_t base = st + 32768 + bWarpOff + nf2 * 2048 + bswz[kf];
                ldsm_x4(tmp, base);
                bh[2 * nf2 + 0][0] = tmp[0]; bh[2 * nf2 + 0][1] = tmp[1];
                bh[2 * nf2 + 1][0] = tmp[2]; bh[2 * nf2 + 1][1] = tmp[3];
                ldsm_x4(tmp, base + 16384);
                bl[2 * nf2 + 0][0] = tmp[0]; bl[2 * nf2 + 0][1] = tmp[1];
                bl[2 * nf2 + 1][0] = tmp[2]; bl[2 * nf2 + 1][1] = tmp[3];
            }
#pragma unroll
            for (int mf = 0; mf < 4; ++mf)
#pragma unroll
                for (int nf = 0; nf < 4; ++nf) {
                    mma16816(acc[mf][nf], ah[mf], bh[nf]);
                    mma16816(acc[mf][nf], ah[mf], bl[nf]);
                    mma16816(acc[mf][nf], al[mf], bh[nf]);
                }
        }
        __syncthreads();
    }

    const int r0 = brow + wm * 64 + (lane >> 2);
    const int c0 = bcol + wn * 32 + 2 * (lane & 3);
#pragma unroll
    for (int mf = 0; mf < 4; ++mf) {
#pragma unroll
        for (int nf = 0; nf < 4; ++nf) {
            int col = c0 + nf * 8;
            float b0 = bias[col], b1 = bias[col + 1];
            int ra = r0 + mf * 16;
            float2 o0 = make_float2(acc[mf][nf][0] + b0, acc[mf][nf][1] + b1);
            float2 o1 = make_float2(acc[mf][nf][2] + b0, acc[mf][nf][3] + b1);
            *reinterpret_cast<float2*>(&C[(size_t)ra * DD + col]) = o0;
            *reinterpret_cast<float2*>(&C[(size_t)(ra + 8) * DD + col]) = o1;
        }
    }
}

// ---------------------------------------------------------------------------
// Tensor-core flash attention (causal), fp16 MMA, fp32 accum.
// Grid: (S/64, H, B). Block: 128 threads = 4 warps, 16 q-rows per warp.
// K tile in smem as [key][dim] fp16 (SW128); V tile stored TRANSPOSED as
// [dim][key] fp16 so the PV B-operand uses the identical no-trans ldmatrix
// path proven by the GEMM. QK accumulator layout == PV A-operand layout.
// ---------------------------------------------------------------------------
__global__ void __launch_bounds__(128) attn_mma(
    const float* __restrict__ Q,
    const float* __restrict__ K,
    const float* __restrict__ V,
    float* __restrict__ Y)
{
    __shared__ char sm[16384];          // [0,8K)=K tile, [8K,16K)=V^T tile
    const uint32_t ksb = smem_u32(sm);
    const uint32_t vtb = ksb + 8192;

    const int b    = blockIdx.z;
    const int h    = blockIdx.y;
    const int qt   = blockIdx.x;
    const int tid  = threadIdx.x;
    const int lane = tid & 31;
    const int warp = tid >> 5;
    const int bS   = b * SS;
    const int row0 = qt * 64 + warp * 16 + (lane >> 2);   // global q row
    const int row1 = row0 + 8;

    // --- Q fragments (A-operand), scale = (1/32) * log2(e) folded in ---
    const float qscale = 0.03125f * 1.44269504f;
    uint32_t aq[4][4];
    {
        const float* qp0 = Q + (size_t)(bS + row0) * DD + h * HD;
        const float* qp1 = qp0 + 8 * DD;
#pragma unroll
        for (int kk = 0; kk < 4; ++kk) {
            int k0 = kk * 16 + 2 * (lane & 3);
            float2 v00 = *reinterpret_cast<const float2*>(qp0 + k0);
            float2 v10 = *reinterpret_cast<const float2*>(qp1 + k0);
            float2 v01 = *reinterpret_cast<const float2*>(qp0 + k0 + 8);
            float2 v11 = *reinterpret_cast<const float2*>(qp1 + k0 + 8);
            aq[kk][0] = packh2(v00.x * qscale, v00.y * qscale);
            aq[kk][1] = packh2(v10.x * qscale, v10.y * qscale);
            aq[kk][2] = packh2(v01.x * qscale, v01.y * qscale);
            aq[kk][3] = packh2(v11.x * qscale, v11.y * qscale);
        }
    }

    // ldmatrix swizzled offsets (same recipe as GEMM B path)
    const uint32_t bRowPart =
        (uint32_t)((lane & 7) + ((lane >> 4) << 3)) * 128 + (((lane >> 3) & 1) << 4);
    uint32_t kswz[4];
#pragma unroll
    for (int kk = 0; kk < 4; ++kk)
        kswz[kk] = SWZ(bRowPart + kk * 32);

    float oacc[8][4];
#pragma unroll
    for (int j = 0; j < 8; ++j)
#pragma unroll
        for (int t = 0; t < 4; ++t)
            oacc[j][t] = 0.0f;
    float m0 = -1e30f, m1 = -1e30f, l0 = 0.0f, l1 = 0.0f;

    const int nkt = qt + 1;
    for (int kt = 0; kt < nkt; ++kt) {
        if (kt) __syncthreads();
        // ---- load K tile (as-is) and V tile (transposed), fp32->fp16 ----
#pragma unroll
        for (int i = 0; i < 8; ++i) {
            int chunk = tid + i * 128;         // 0..1023
            int key   = chunk >> 4;
            int d4    = (chunk & 15) * 4;
            size_t off = (size_t)(bS + kt * 64 + key) * DD + h * HD + d4;
            float4 kv = *reinterpret_cast<const float4*>(K + off);
            uint2 kp;
            kp.x = packh2(kv.x, kv.y);
            kp.y = packh2(kv.z, kv.w);
            *reinterpret_cast<uint2*>(sm + SWZ(key * 128 + d4 * 2)) = kp;
            float4 vv = *reinterpret_cast<const float4*>(V + off);
            __half* vp = reinterpret_cast<__half*>(sm + 8192);
            *reinterpret_cast<__half*>(sm + 8192 + SWZ((d4 + 0) * 128 + key * 2)) =
                __float2half_rn(vv.x);
            *reinterpret_cast<__half*>(sm + 8192 + SWZ((d4 + 1) * 128 + key * 2)) =
                __float2half_rn(vv.y);
            *reinterpret_cast<__half*>(sm + 8192 + SWZ((d4 + 2) * 128 + key * 2)) =
                __float2half_rn(vv.z);
            *reinterpret_cast<__half*>(sm + 8192 + SWZ((d4 + 3) * 128 + key * 2)) =
                __float2half_rn(vv.w);
            (void)vp;
        }
        __syncthreads();

        // ---- S = Q K^T (log2 domain) ----
        float sacc[8][4];
#pragma unroll
        for (int j = 0; j < 8; ++j)
#pragma unroll
            for (int t = 0; t < 4; ++t)
                sacc[j][t] = 0.0f;
#pragma unroll
        for (int kk = 0; kk < 4; ++kk) {
#pragma unroll
            for (int nf2 = 0; nf2 < 4; ++nf2) {
                uint32_t tmp[4];
                ldsm_x4(tmp, ksb + nf2 * 2048 + kswz[kk]);
                mma16816h(sacc[2 * nf2 + 0], aq[kk], tmp[0], tmp[1]);
                mma16816h(sacc[2 * nf2 + 1], aq[kk], tmp[2], tmp[3]);
            }
        }

        // ---- causal mask (only the diagonal tile kt == qt) ----
        if (kt == qt) {
#pragma unroll
            for (int j = 0; j < 8; ++j) {
                int c = kt * 64 + j * 8 + 2 * (lane & 3);
                if (c     > row0) sacc[j][0] = -1e30f;
                if (c + 1 > row0) sacc[j][1] = -1e30f;
                if (c     > row1) sacc[j][2] = -1e30f;
                if (c + 1 > row1) sacc[j][3] = -1e30f;
            }
        }

        // ---- online softmax ----
        float mt0 = sacc[0][0], mt1 = sacc[0][2];
#pragma unroll
        for (int j = 0; j < 8; ++j) {
            mt0 = fmaxf(mt0, fmaxf(sacc[j][0], sacc[j][1]));
            mt1 = fmaxf(mt1, fmaxf(sacc[j][2], sacc[j][3]));
        }
        mt0 = fmaxf(mt0, __shfl_xor_sync(0xffffffffu, mt0, 1));
        mt0 = fmaxf(mt0, __shfl_xor_sync(0xffffffffu, mt0, 2));
        mt1 = fmaxf(mt1, __shfl_xor_sync(0xffffffffu, mt1, 1));
        mt1 = fmaxf(mt1, __shfl_xor_sync(0xffffffffu, mt1, 2));

        float mn0 = fmaxf(m0, mt0);
        float mn1 = fmaxf(m1, mt1);
        float corr0 = ex2(m0 - mn0);
        float corr1 = ex2(m1 - mn1);
        m0 = mn0; m1 = mn1;
        l0 *= corr0; l1 *= corr1;
#pragma unroll
        for (int j = 0; j < 8; ++j) {
            oacc[j][0] *= corr0; oacc[j][1] *= corr0;
            oacc[j][2] *= corr1; oacc[j][3] *= corr1;
        }

        uint32_t ph[8][2];
#pragma unroll
        for (int j = 0; j < 8; ++j) {
            float p00 = ex2(sacc[j][0] - m0);
            float p01 = ex2(sacc[j][1] - m0);
            float p10 = ex2(sacc[j][2] - m1);
            float p11 = ex2(sacc[j][3] - m1);
            l0 += p00 + p01;
            l1 += p10 + p11;
            ph[j][0] = packh2(p00, p01);
            ph[j][1] = packh2(p10, p11);
        }

        // ---- O += P V ----
#pragma unroll
        for (int kk = 0; kk < 4; ++kk) {
            uint32_t ap[4] = { ph[2 * kk][0], ph[2 * kk][1],
                               ph[2 * kk + 1][0], ph[2 * kk + 1][1] };
#pragma unroll
            for (int nf2 = 0; nf2 < 4; ++nf2) {
                uint32_t tmp[4];
                ldsm_x4(tmp, vtb + nf2 * 2048 + kswz[kk]);
                mma16816h(oacc[2 * nf2 + 0], ap, tmp[0], tmp[1]);
                mma16816h(oacc[2 * nf2 + 1], ap, tmp[2], tmp[3]);
            }
        }
    }

    // ---- finalize ----
    l0 += __shfl_xor_sync(0xffffffffu, l0, 1);
    l0 += __shfl_xor_sync(0xffffffffu, l0, 2);
    l1 += __shfl_xor_sync(0xffffffffu, l1, 1);
    l1 += __shfl_xor_sync(0xffffffffu, l1, 2);
    const float inv0 = 1.0f / l0;
    const float inv1 = 1.0f / l1;

    float* y0 = Y + (size_t)(bS + row0) * DD + h * HD;
    float* y1 = Y + (size_t)(bS + row1) * DD + h * HD;
#pragma unroll
    for (int j = 0; j < 8; ++j) {
        int col = j * 8 + 2 * (lane & 3);
        float2 o0 = make_float2(oacc[j][0] * inv0, oacc[j][1] * inv0);
        float2 o1 = make_float2(oacc[j][2] * inv1, oacc[j][3] * inv1);
        *reinterpret_cast<float2*>(y0 + col) = o0;
        *reinterpret_cast<float2*>(y1 + col) = o1;
    }
}

// ---------------------------------------------------------------------------
// Launch
// ---------------------------------------------------------------------------
extern "C" void kernel_launch(void* const* d_in, const int* in_sizes, int n_in,
                              void* d_out, int out_size)
{
    (void)in_sizes; (void)n_in; (void)out_size;
    const float* x  = (const float*)d_in[0];
    const float* Wq = (const float*)d_in[1];
    const float* bq = (const float*)d_in[2];
    const float* Wk = (const float*)d_in[3];
    const float* bk = (const float*)d_in[4];
    const float* Wv = (const float*)d_in[5];
    const float* bv = (const float*)d_in[6];
    const float* Wp = (const float*)d_in[7];
    const float* bp = (const float*)d_in[8];
    float* out = (float*)d_out;

    float *Qb, *Kb, *Vb, *Yb;
    __nv_bfloat16 *Ahi, *Alo, *Whi, *Wlo;
    cudaGetSymbolAddress((void**)&Qb, g_Q);
    cudaGetSymbolAddress((void**)&Kb, g_K);
    cudaGetSymbolAddress((void**)&Vb, g_V);
    cudaGetSymbolAddress((void**)&Yb, g_Yb);
    cudaGetSymbolAddress((void**)&Ahi, g_Ahi);
    cudaGetSymbolAddress((void**)&Alo, g_Alo);
    cudaGetSymbolAddress((void**)&Whi, g_Whi);
    cudaGetSymbolAddress((void**)&Wlo, g_Wlo);

    cudaFuncSetAttribute(gemm_mma_bias,
                         cudaFuncAttributeMaxDynamicSharedMemorySize, GEMM_SMEM);

    const int nX4 = MM * DD / 4;
    const int nW4 = DD * DD / 4;
    dim3 gg(DD / 128, MM / 128);

    split_kernel<<<(nX4 + 255) / 256, 256>>>(
        (const float4*)x, (uint2*)Ahi, (uint2*)Alo, nX4);

    split_kernel<<<(nW4 + 255) / 256, 256>>>(
        (const float4*)Wq, (uint2*)Whi, (uint2*)Wlo, nW4);
    gemm_mma_bias<<<gg, 256, GEMM_SMEM>>>(Ahi, Alo, Whi, Wlo, bq, Qb);

    split_kernel<<<(nW4 + 255) / 256, 256>>>(
        (const float4*)Wk, (uint2*)Whi, (uint2*)Wlo, nW4);
    gemm_mma_bias<<<gg, 256, GEMM_SMEM>>>(Ahi, Alo, Whi, Wlo, bk, Kb);

    split_kernel<<<(nW4 + 255) / 256, 256>>>(
        (const float4*)Wv, (uint2*)Whi, (uint2*)Wlo, nW4);
    gemm_mma_bias<<<gg, 256, GEMM_SMEM>>>(Ahi, Alo, Whi, Wlo, bv, Vb);

    attn_mma<<<dim3(SS / 64, HH, BB), 128>>>(Qb, Kb, Vb, Yb);

    split_kernel<<<(nX4 + 255) / 256, 256>>>(
        (const float4*)Yb, (uint2*)Ahi, (uint2*)Alo, nX4);
    split_kernel<<<(nW4 + 255) / 256, 256>>>(
        (const float4*)Wp, (uint2*)Whi, (uint2*)Wlo, nW4);
    gemm_mma_bias<<<gg, 256, GEMM_SMEM>>>(Ahi, Alo, Whi, Wlo, bp, out);
}

// round 5
// speedup vs baseline: 4.9714x; 1.3334x over previous
#include <cuda_runtime.h>
#include <cuda_bf16.h>
#include <cuda_fp16.h>
#include <cstdint>
#include <cstddef>

// Problem constants
#define BB 2
#define SS 2048
#define DD 1024
#define HH 16
#define HD 64
#define MM (BB*SS)   // 4096
#define NQT (SS/64)  // 32 q-tiles per (b,h)

#define QSCALE (0.03125f * 1.44269504f)   // 1/sqrt(D) * log2(e)

// Scratch buffers (device globals; no allocation allowed)
__device__ __half g_Qh[MM * DD];
__device__ __half g_Kh[MM * DD];
__device__ __half g_Vh[MM * DD];
__device__ __nv_bfloat16 g_Ahi[MM * DD];
__device__ __nv_bfloat16 g_Alo[MM * DD];
__device__ __nv_bfloat16 g_Whi[4 * DD * DD];
__device__ __nv_bfloat16 g_Wlo[4 * DD * DD];

// ---------------------------------------------------------------------------
// Helpers
// ---------------------------------------------------------------------------
__device__ __forceinline__ uint32_t smem_u32(const void* p) {
    uint32_t a;
    asm("{ .reg .u64 t; cvta.to.shared.u64 t, %1; cvt.u32.u64 %0, t; }"
        : "=r"(a) : "l"(p));
    return a;
}

#define SWZ(off) ((uint32_t)(off) ^ ((((uint32_t)(off)) >> 3) & 0x70))

__device__ __forceinline__ void cp_async16(uint32_t dst, const void* src) {
    asm volatile("cp.async.cg.shared.global [%0], [%1], 16;"
                 :: "r"(dst), "l"(src) : "memory");
}
__device__ __forceinline__ void cp_commit() {
    asm volatile("cp.async.commit_group;" ::: "memory");
}
template <int N>
__device__ __forceinline__ void cp_wait() {
    asm volatile("cp.async.wait_group %0;" :: "n"(N) : "memory");
}

__device__ __forceinline__ void ldsm_x4(uint32_t* r, uint32_t addr) {
    asm volatile("ldmatrix.sync.aligned.m8n8.x4.shared.b16 {%0,%1,%2,%3}, [%4];"
                 : "=r"(r[0]), "=r"(r[1]), "=r"(r[2]), "=r"(r[3])
                 : "r"(addr));
}

__device__ __forceinline__ void ldsm_x4_t(uint32_t* r, uint32_t addr) {
    asm volatile("ldmatrix.sync.aligned.m8n8.x4.trans.shared.b16 {%0,%1,%2,%3}, [%4];"
                 : "=r"(r[0]), "=r"(r[1]), "=r"(r[2]), "=r"(r[3])
                 : "r"(addr));
}

__device__ __forceinline__ void mma16816(float* d, const uint32_t* a,
                                         const uint32_t* b) {
    asm volatile(
        "mma.sync.aligned.m16n8k16.row.col.f32.bf16.bf16.f32 "
        "{%0,%1,%2,%3}, {%4,%5,%6,%7}, {%8,%9}, {%0,%1,%2,%3};"
        : "+f"(d[0]), "+f"(d[1]), "+f"(d[2]), "+f"(d[3])
        : "r"(a[0]), "r"(a[1]), "r"(a[2]), "r"(a[3]), "r"(b[0]), "r"(b[1]));
}

__device__ __forceinline__ void mma16816h(float* d, const uint32_t* a,
                                          uint32_t b0, uint32_t b1) {
    asm volatile(
        "mma.sync.aligned.m16n8k16.row.col.f32.f16.f16.f32 "
        "{%0,%1,%2,%3}, {%4,%5,%6,%7}, {%8,%9}, {%0,%1,%2,%3};"
        : "+f"(d[0]), "+f"(d[1]), "+f"(d[2]), "+f"(d[3])
        : "r"(a[0]), "r"(a[1]), "r"(a[2]), "r"(a[3]), "r"(b0), "r"(b1));
}

__device__ __forceinline__ float ex2(float x) {
    float y;
    asm("ex2.approx.ftz.f32 %0, %1;" : "=f"(y) : "f"(x));
    return y;
}

__device__ __forceinline__ uint32_t packbf2(float a, float b) {
    __nv_bfloat162 h = __floats2bfloat162_rn(a, b);
    return *reinterpret_cast<uint32_t*>(&h);
}

// ---------------------------------------------------------------------------
// Splits: fp32 -> bf16 hi + bf16 lo(residual)
// ---------------------------------------------------------------------------
__device__ __forceinline__ void split4(float4 v, uint2& ho, uint2& loo) {
    __nv_bfloat162 h0 = __float22bfloat162_rn(make_float2(v.x, v.y));
    __nv_bfloat162 h1 = __float22bfloat162_rn(make_float2(v.z, v.w));
    float2 hf0 = __bfloat1622float2(h0);
    float2 hf1 = __bfloat1622float2(h1);
    __nv_bfloat162 l0 = __float22bfloat162_rn(make_float2(v.x - hf0.x, v.y - hf0.y));
    __nv_bfloat162 l1 = __float22bfloat162_rn(make_float2(v.z - hf1.x, v.w - hf1.y));
    ho.x = *reinterpret_cast<uint32_t*>(&h0);
    ho.y = *reinterpret_cast<uint32_t*>(&h1);
    loo.x = *reinterpret_cast<uint32_t*>(&l0);
    loo.y = *reinterpret_cast<uint32_t*>(&l1);
}

__global__ void __launch_bounds__(256) split_kernel(
    const float4* __restrict__ src, uint2* __restrict__ hi,
    uint2* __restrict__ lo, int n4)
{
    int i = blockIdx.x * blockDim.x + threadIdx.x;
    if (i >= n4) return;
    uint2 h, l;
    split4(src[i], h, l);
    hi[i] = h;
    lo[i] = l;
}

__global__ void __launch_bounds__(256) split_w4(
    const float4* __restrict__ w0, const float4* __restrict__ w1,
    const float4* __restrict__ w2, const float4* __restrict__ w3,
    uint2* __restrict__ hi, uint2* __restrict__ lo, int n4)
{
    int z = blockIdx.y;
    const float4* src = (z == 0) ? w0 : (z == 1) ? w1 : (z == 2) ? w2 : w3;
    int i = blockIdx.x * blockDim.x + threadIdx.x;
    if (i >= n4) return;
    uint2 h, l;
    split4(src[i], h, l);
    hi[(size_t)z * n4 + i] = h;
    lo[(size_t)z * n4 + i] = l;
}

// ---------------------------------------------------------------------------
// Shared GEMM mainloop (bf16 3-term split), 128x128 tile, 8 warps.
// Returns accumulators; caller provides epilogue.
// ---------------------------------------------------------------------------
#define ST_BYTES 65536
#define GEMM_SMEM (2 * ST_BYTES)

struct GemmCtx {
    uint32_t sbase;
    int tid, lane, warp, wm, wn, brow, bcol;
};

__device__ __forceinline__ void gemm_mainloop(
    const GemmCtx& g,
    const __nv_bfloat16* __restrict__ Ahi,
    const __nv_bfloat16* __restrict__ Alo,
    const __nv_bfloat16* __restrict__ Whi,
    const __nv_bfloat16* __restrict__ Wlo,
    float acc[4][4][4])
{
    const int ldr = g.tid >> 3;
    const int ldc = g.tid & 7;
    uint32_t ldswz[4];
#pragma unroll
    for (int i = 0; i < 4; ++i)
        ldswz[i] = SWZ((ldr + i * 32) * 128 + ldc * 16);

    auto issue_stage = [&](int kt, int buf) {
        const uint32_t st = g.sbase + buf * ST_BYTES;
        const int k0 = kt * 64;
#pragma unroll
        for (int i = 0; i < 4; ++i) {
            int r = ldr + i * 32;
            size_t offA = (size_t)(g.brow + r) * DD + k0 + ldc * 8;
            size_t offB = (size_t)(g.bcol + r) * DD + k0 + ldc * 8;
            cp_async16(st + 0     + ldswz[i], Ahi + offA);
            cp_async16(st + 16384 + ldswz[i], Alo + offA);
            cp_async16(st + 32768 + ldswz[i], Whi + offB);
            cp_async16(st + 49152 + ldswz[i], Wlo + offB);
        }
        cp_commit();
    };

    const uint32_t aRowPart = (uint32_t)(g.lane & 15) * 128 + ((g.lane >> 4) << 4);
    const uint32_t bRowPart =
        (uint32_t)((g.lane & 7) + ((g.lane >> 4) << 3)) * 128 +
        (((g.lane >> 3) & 1) << 4);
    uint32_t aswz[4], bswz[4];
#pragma unroll
    for (int kf = 0; kf < 4; ++kf) {
        aswz[kf] = SWZ(aRowPart + kf * 32);
        bswz[kf] = SWZ(bRowPart + kf * 32);
    }
    const uint32_t aWarpOff = g.wm * 8192;
    const uint32_t bWarpOff = g.wn * 4096;

    issue_stage(0, 0);

    for (int kt = 0; kt < 16; ++kt) {
        const int buf = kt & 1;
        if (kt < 15) {
            issue_stage(kt + 1, buf ^ 1);
            cp_wait<1>();
        } else {
            cp_wait<0>();
        }
        __syncthreads();

        const uint32_t st = g.sbase + buf * ST_BYTES;
#pragma unroll
        for (int kf = 0; kf < 4; ++kf) {
            uint32_t ah[4][4], al[4][4], bh[4][2], bl[4][2];
#pragma unroll
            for (int mf = 0; mf < 4; ++mf) {
                uint32_t base = st + aWarpOff + mf * 2048 + aswz[kf];
                ldsm_x4(ah[mf], base);
                ldsm_x4(al[mf], base + 16384);
            }
#pragma unroll
            for (int nf2 = 0; nf2 < 2; ++nf2) {
                uint32_t tmp[4];
                uint32_t base = st + 32768 + bWarpOff + nf2 * 2048 + bswz[kf];
                ldsm_x4(tmp, base);
                bh[2 * nf2 + 0][0] = tmp[0]; bh[2 * nf2 + 0][1] = tmp[1];
                bh[2 * nf2 + 1][0] = tmp[2]; bh[2 * nf2 + 1][1] = tmp[3];
                ldsm_x4(tmp, base + 16384);
                bl[2 * nf2 + 0][0] = tmp[0]; bl[2 * nf2 + 0][1] = tmp[1];
                bl[2 * nf2 + 1][0] = tmp[2]; bl[2 * nf2 + 1][1] = tmp[3];
            }
#pragma unroll
            for (int mf = 0; mf < 4; ++mf)
#pragma unroll
                for (int nf = 0; nf < 4; ++nf) {
                    mma16816(acc[mf][nf], ah[mf], bh[nf]);
                    mma16816(acc[mf][nf], ah[mf], bl[nf]);
                    mma16816(acc[mf][nf], al[mf], bh[nf]);
                }
        }
        __syncthreads();
    }
}

// ---------------------------------------------------------------------------
// Fused QKV GEMM: z selects weight slot / bias / fp16 output / scale.
// ---------------------------------------------------------------------------
__global__ void __launch_bounds__(256) gemm_qkv(
    const __nv_bfloat16* __restrict__ Ahi,
    const __nv_bfloat16* __restrict__ Alo,
    const __nv_bfloat16* __restrict__ WhiBase,
    const __nv_bfloat16* __restrict__ WloBase,
    const float* __restrict__ bq, const float* __restrict__ bk,
    const float* __restrict__ bv,
    __half* __restrict__ Qh, __half* __restrict__ Kh, __half* __restrict__ Vh)
{
    extern __shared__ char smem[];
    const int z = blockIdx.z;
    const __nv_bfloat16* Whi = WhiBase + (size_t)z * DD * DD;
    const __nv_bfloat16* Wlo = WloBase + (size_t)z * DD * DD;
    const float* bias = (z == 0) ? bq : (z == 1) ? bk : bv;
    __half* Ch = (z == 0) ? Qh : (z == 1) ? Kh : Vh;
    const float scl = (z == 0) ? QSCALE : 1.0f;

    GemmCtx g;
    g.sbase = smem_u32(smem);
    g.tid = threadIdx.x; g.lane = g.tid & 31; g.warp = g.tid >> 5;
    g.wm = g.warp >> 2; g.wn = g.warp & 3;
    g.brow = blockIdx.y * 128; g.bcol = blockIdx.x * 128;

    float acc[4][4][4];
#pragma unroll
    for (int i = 0; i < 4; ++i)
#pragma unroll
        for (int j = 0; j < 4; ++j)
#pragma unroll
            for (int t = 0; t < 4; ++t) acc[i][j][t] = 0.0f;

    gemm_mainloop(g, Ahi, Alo, Whi, Wlo, acc);

    const int r0 = g.brow + g.wm * 64 + (g.lane >> 2);
    const int c0 = g.bcol + g.wn * 32 + 2 * (g.lane & 3);
#pragma unroll
    for (int mf = 0; mf < 4; ++mf) {
#pragma unroll
        for (int nf = 0; nf < 4; ++nf) {
            int col = c0 + nf * 8;
            float b0 = bias[col], b1 = bias[col + 1];
            int ra = r0 + mf * 16;
            __half2 o0 = __floats2half2_rn((acc[mf][nf][0] + b0) * scl,
                                           (acc[mf][nf][1] + b1) * scl);
            __half2 o1 = __floats2half2_rn((acc[mf][nf][2] + b0) * scl,
                                           (acc[mf][nf][3] + b1) * scl);
            *reinterpret_cast<__half2*>(&Ch[(size_t)ra * DD + col]) = o0;
            *reinterpret_cast<__half2*>(&Ch[(size_t)(ra + 8) * DD + col]) = o1;
        }
    }
}

// ---------------------------------------------------------------------------
// Output-projection GEMM: fp32 out + bias.
// ---------------------------------------------------------------------------
__global__ void __launch_bounds__(256) gemm_p(
    const __nv_bfloat16* __restrict__ Ahi,
    const __nv_bfloat16* __restrict__ Alo,
    const __nv_bfloat16* __restrict__ Whi,
    const __nv_bfloat16* __restrict__ Wlo,
    const float* __restrict__ bias,
    float* __restrict__ C)
{
    extern __shared__ char smem[];
    GemmCtx g;
    g.sbase = smem_u32(smem);
    g.tid = threadIdx.x; g.lane = g.tid & 31; g.warp = g.tid >> 5;
    g.wm = g.warp >> 2; g.wn = g.warp & 3;
    g.brow = blockIdx.y * 128; g.bcol = blockIdx.x * 128;

    float acc[4][4][4];
#pragma unroll
    for (int i = 0; i < 4; ++i)
#pragma unroll
        for (int j = 0; j < 4; ++j)
#pragma unroll
            for (int t = 0; t < 4; ++t) acc[i][j][t] = 0.0f;

    gemm_mainloop(g, Ahi, Alo, Whi, Wlo, acc);

    const int r0 = g.brow + g.wm * 64 + (g.lane >> 2);
    const int c0 = g.bcol + g.wn * 32 + 2 * (g.lane & 3);
#pragma unroll
    for (int mf = 0; mf < 4; ++mf) {
#pragma unroll
        for (int nf = 0; nf < 4; ++nf) {
            int col = c0 + nf * 8;
            float b0 = bias[col], b1 = bias[col + 1];
            int ra = r0 + mf * 16;
            float2 o0 = make_float2(acc[mf][nf][0] + b0, acc[mf][nf][1] + b1);
            float2 o1 = make_float2(acc[mf][nf][2] + b0, acc[mf][nf][3] + b1);
            *reinterpret_cast<float2*>(&C[(size_t)ra * DD + col]) = o0;
            *reinterpret_cast<float2*>(&C[(size_t)(ra + 8) * DD + col]) = o1;
        }
    }
}

// ---------------------------------------------------------------------------
// Tensor-core flash attention, fp16 in, bf16 hi/lo split out.
// Grid: (NQT/2, H, B); each block does q-tiles {qa, 31-qa} (33 key-tiles).
// K,V tiles cp.async double-buffered; V consumed via ldmatrix.trans.
// ---------------------------------------------------------------------------
__global__ void __launch_bounds__(128) attn_mma(
    const __half* __restrict__ Qh,
    const __half* __restrict__ Kh,
    const __half* __restrict__ Vh,
    __nv_bfloat16* __restrict__ Yhi,
    __nv_bfloat16* __restrict__ Ylo)
{
    __shared__ char sm[32768];            // 2 bufs x (K 8KB + V 8KB)
    const uint32_t sb = smem_u32(sm);

    const int b    = blockIdx.z;
    const int h    = blockIdx.y;
    const int qa   = blockIdx.x;
    const int tid  = threadIdx.x;
    const int lane = tid & 31;
    const int warp = tid >> 5;
    const int bS   = b * SS;

    // ldmatrix offsets
    const uint32_t bRowPart =
        (uint32_t)((lane & 7) + ((lane >> 4) << 3)) * 128 + (((lane >> 3) & 1) << 4);
    uint32_t kswz[4];
#pragma unroll
    for (int kk = 0; kk < 4; ++kk)
        kswz[kk] = SWZ(bRowPart + kk * 32);
    const uint32_t vRowPart = (uint32_t)(lane & 15) * 128 + ((lane >> 4) << 4);
    uint32_t vswz[4];
#pragma unroll
    for (int nf2 = 0; nf2 < 4; ++nf2)
        vswz[nf2] = SWZ(vRowPart + nf2 * 32);

    // cp.async chunk indexing: 4 chunks each for K and V per tile
    const int ck  = tid >> 3;            // base key (i=0); +32 per i... (below)
    const int ccb = (tid & 7) * 16;      // byte within 128B row
    uint32_t lsw[4];
#pragma unroll
    for (int i = 0; i < 4; ++i)
        lsw[i] = SWZ((ck + i * 16) * 128 + ccb);

    auto issue_tile = [&](int kt, int buf) {
        uint32_t kb = sb + buf * 16384;
        uint32_t vb = kb + 8192;
#pragma unroll
        for (int i = 0; i < 4; ++i) {
            int key = ck + i * 16;
            const char* base = reinterpret_cast<const char*>(
                (size_t)(bS + kt * 64 + key) * DD + h * HD) ;
            (void)base;
            size_t off = ((size_t)(bS + kt * 64 + key) * DD + h * HD) * 2 + ccb;
            cp_async16(kb + lsw[i], reinterpret_cast<const char*>(Kh) + off);
            cp_async16(vb + lsw[i], reinterpret_cast<const char*>(Vh) + off);
        }
        cp_commit();
    };

#pragma unroll 1
    for (int pass = 0; pass < 2; ++pass) {
        const int qt = pass ? (NQT - 1 - qa) : qa;
        const int row0 = qt * 64 + warp * 16 + (lane >> 2);
        const int row1 = row0 + 8;
        __syncthreads();   // protect smem reuse across passes

        // Q fragments (fp16 global, already scaled)
        uint32_t aq[4][4];
        {
            const __half* qp0 = Qh + (size_t)(bS + row0) * DD + h * HD;
            const __half* qp1 = qp0 + 8 * DD;
#pragma unroll
            for (int kk = 0; kk < 4; ++kk) {
                int k0 = kk * 16 + 2 * (lane & 3);
                aq[kk][0] = *reinterpret_cast<const uint32_t*>(qp0 + k0);
                aq[kk][1] = *reinterpret_cast<const uint32_t*>(qp1 + k0);
                aq[kk][2] = *reinterpret_cast<const uint32_t*>(qp0 + k0 + 8);
                aq[kk][3] = *reinterpret_cast<const uint32_t*>(qp1 + k0 + 8);
            }
        }

        float oacc[8][4];
#pragma unroll
        for (int j = 0; j < 8; ++j)
#pragma unroll
            for (int t = 0; t < 4; ++t) oacc[j][t] = 0.0f;
        float m0 = -1e30f, m1 = -1e30f, l0 = 0.0f, l1 = 0.0f;

        issue_tile(0, 0);

#pragma unroll 1
        for (int kt = 0; kt <= qt; ++kt) {
            const int buf = kt & 1;
            if (kt < qt) {
                issue_tile(kt + 1, buf ^ 1);
                cp_wait<1>();
            } else {
                cp_wait<0>();
            }
            __syncthreads();

            const uint32_t kb = sb + buf * 16384;
            const uint32_t vb = kb + 8192;

            // ---- S = Q K^T (log2 domain) ----
            float sacc[8][4];
#pragma unroll
            for (int j = 0; j < 8; ++j)
#pragma unroll
                for (int t = 0; t < 4; ++t) sacc[j][t] = 0.0f;
#pragma unroll
            for (int kk = 0; kk < 4; ++kk) {
#pragma unroll
                for (int nf2 = 0; nf2 < 4; ++nf2) {
                    uint32_t tmp[4];
                    ldsm_x4(tmp, kb + nf2 * 2048 + kswz[kk]);
                    mma16816h(sacc[2 * nf2 + 0], aq[kk], tmp[0], tmp[1]);
                    mma16816h(sacc[2 * nf2 + 1], aq[kk], tmp[2], tmp[3]);
                }
            }

            if (kt == qt) {
#pragma unroll
                for (int j = 0; j < 8; ++j) {
                    int c = kt * 64 + j * 8 + 2 * (lane & 3);
                    if (c     > row0) sacc[j][0] = -1e30f;
                    if (c + 1 > row0) sacc[j][1] = -1e30f;
                    if (c     > row1) sacc[j][2] = -1e30f;
                    if (c + 1 > row1) sacc[j][3] = -1e30f;
                }
            }

            // ---- online softmax ----
            float mt0 = sacc[0][0], mt1 = sacc[0][2];
#pragma unroll
            for (int j = 0; j < 8; ++j) {
                mt0 = fmaxf(mt0, fmaxf(sacc[j][0], sacc[j][1]));
                mt1 = fmaxf(mt1, fmaxf(sacc[j][2], sacc[j][3]));
            }
            mt0 = fmaxf(mt0, __shfl_xor_sync(0xffffffffu, mt0, 1));
            mt0 = fmaxf(mt0, __shfl_xor_sync(0xffffffffu, mt0, 2));
            mt1 = fmaxf(mt1, __shfl_xor_sync(0xffffffffu, mt1, 1));
            mt1 = fmaxf(mt1, __shfl_xor_sync(0xffffffffu, mt1, 2));

            float mn0 = fmaxf(m0, mt0);
            float mn1 = fmaxf(m1, mt1);
            float corr0 = ex2(m0 - mn0);
            float corr1 = ex2(m1 - mn1);
            m0 = mn0; m1 = mn1;
            l0 *= corr0; l1 *= corr1;
#pragma unroll
            for (int j = 0; j < 8; ++j) {
                oacc[j][0] *= corr0; oacc[j][1] *= corr0;
                oacc[j][2] *= corr1; oacc[j][3] *= corr1;
            }

            uint32_t ph[8][2];
#pragma unroll
            for (int j = 0; j < 8; ++j) {
                float p00 = ex2(sacc[j][0] - m0);
                float p01 = ex2(sacc[j][1] - m0);
                float p10 = ex2(sacc[j][2] - m1);
                float p11 = ex2(sacc[j][3] - m1);
                l0 += p00 + p01;
                l1 += p10 + p11;
                __half2 h0 = __floats2half2_rn(p00, p01);
                __half2 h1 = __floats2half2_rn(p10, p11);
                ph[j][0] = *reinterpret_cast<uint32_t*>(&h0);
                ph[j][1] = *reinterpret_cast<uint32_t*>(&h1);
            }

            // ---- O += P V  (V via ldmatrix.trans on [key][dim]) ----
#pragma unroll
            for (int kk = 0; kk < 4; ++kk) {
                uint32_t ap[4] = { ph[2 * kk][0], ph[2 * kk][1],
                                   ph[2 * kk + 1][0], ph[2 * kk + 1][1] };
#pragma unroll
                for (int nf2 = 0; nf2 < 4; ++nf2) {
                    uint32_t tmp[4];
                    ldsm_x4_t(tmp, vb + kk * 2048 + vswz[nf2]);
                    mma16816h(oacc[2 * nf2 + 0], ap, tmp[0], tmp[1]);
                    mma16816h(oacc[2 * nf2 + 1], ap, tmp[2], tmp[3]);
                }
            }
            __syncthreads();
        }

        // ---- finalize: write Y as bf16 hi/lo split ----
        l0 += __shfl_xor_sync(0xffffffffu, l0, 1);
        l0 += __shfl_xor_sync(0xffffffffu, l0, 2);
        l1 += __shfl_xor_sync(0xffffffffu, l1, 1);
        l1 += __shfl_xor_sync(0xffffffffu, l1, 2);
        const float inv0 = 1.0f / l0;
        const float inv1 = 1.0f / l1;

        size_t o0 = (size_t)(bS + row0) * DD + h * HD;
        size_t o1 = (size_t)(bS + row1) * DD + h * HD;
#pragma unroll
        for (int j = 0; j < 8; ++j) {
            int col = j * 8 + 2 * (lane & 3);
            float y00 = oacc[j][0] * inv0, y01 = oacc[j][1] * inv0;
            float y10 = oacc[j][2] * inv1, y11 = oacc[j][3] * inv1;
            float h00 = __bfloat162float(__float2bfloat16_rn(y00));
            float h01 = __bfloat162float(__float2bfloat16_rn(y01));
            float h10 = __bfloat162float(__float2bfloat16_rn(y10));
            float h11 = __bfloat162float(__float2bfloat16_rn(y11));
            *reinterpret_cast<uint32_t*>(&Yhi[o0 + col]) = packbf2(y00, y01);
            *reinterpret_cast<uint32_t*>(&Yhi[o1 + col]) = packbf2(y10, y11);
            *reinterpret_cast<uint32_t*>(&Ylo[o0 + col]) =
                packbf2(y00 - h00, y01 - h01);
            *reinterpret_cast<uint32_t*>(&Ylo[o1 + col]) =
                packbf2(y10 - h10, y11 - h11);
        }
    }
}

// ---------------------------------------------------------------------------
// Launch
// ---------------------------------------------------------------------------
extern "C" void kernel_launch(void* const* d_in, const int* in_sizes, int n_in,
                              void* d_out, int out_size)
{
    (void)in_sizes; (void)n_in; (void)out_size;
    const float* x  = (const float*)d_in[0];
    const float* Wq = (const float*)d_in[1];
    const float* bq = (const float*)d_in[2];
    const float* Wk = (const float*)d_in[3];
    const float* bk = (const float*)d_in[4];
    const float* Wv = (const float*)d_in[5];
    const float* bv = (const float*)d_in[6];
    const float* Wp = (const float*)d_in[7];
    const float* bp = (const float*)d_in[8];
    float* out = (float*)d_out;

    __half *Qh, *Kh, *Vh;
    __nv_bfloat16 *Ahi, *Alo, *Whi, *Wlo;
    cudaGetSymbolAddress((void**)&Qh, g_Qh);
    cudaGetSymbolAddress((void**)&Kh, g_Kh);
    cudaGetSymbolAddress((void**)&Vh, g_Vh);
    cudaGetSymbolAddress((void**)&Ahi, g_Ahi);
    cudaGetSymbolAddress((void**)&Alo, g_Alo);
    cudaGetSymbolAddress((void**)&Whi, g_Whi);
    cudaGetSymbolAddress((void**)&Wlo, g_Wlo);

    cudaFuncSetAttribute(gemm_qkv,
                         cudaFuncAttributeMaxDynamicSharedMemorySize, GEMM_SMEM);
    cudaFuncSetAttribute(gemm_p,
                         cudaFuncAttributeMaxDynamicSharedMemorySize, GEMM_SMEM);

    const int nX4 = MM * DD / 4;
    const int nW4 = DD * DD / 4;

    split_kernel<<<(nX4 + 255) / 256, 256>>>(
        (const float4*)x, (uint2*)Ahi, (uint2*)Alo, nX4);
    split_w4<<<dim3((nW4 + 255) / 256, 4), 256>>>(
        (const float4*)Wq, (const float4*)Wk, (const float4*)Wv,
        (const float4*)Wp, (uint2*)Whi, (uint2*)Wlo, nW4);

    gemm_qkv<<<dim3(DD / 128, MM / 128, 3), 256, GEMM_SMEM>>>(
        Ahi, Alo, Whi, Wlo, bq, bk, bv, Qh, Kh, Vh);

    attn_mma<<<dim3(NQT / 2, HH, BB), 128>>>(Qh, Kh, Vh, Ahi, Alo);

    gemm_p<<<dim3(DD / 128, MM / 128), 256, GEMM_SMEM>>>(
        Ahi, Alo, Whi + (size_t)3 * DD * DD, Wlo + (size_t)3 * DD * DD,
        bp, out);
}

// round 6
// speedup vs baseline: 5.0349x; 1.0128x over previous
#include <cuda_runtime.h>
#include <cuda_bf16.h>
#include <cuda_fp16.h>
#include <cstdint>
#include <cstddef>

// Problem constants
#define BB 2
#define SS 2048
#define DD 1024
#define HH 16
#define HD 64
#define MM (BB*SS)   // 4096
#define NQT (SS/64)  // 32 q-tiles per (b,h)

#define QSCALE (0.03125f * 1.44269504f)   // 1/sqrt(D) * log2(e)

// Scratch buffers (device globals; no allocation allowed)
__device__ __half g_Qh[MM * DD];
__device__ __half g_Kh[MM * DD];
__device__ __half g_Vh[MM * DD];
__device__ __nv_bfloat16 g_Ahi[MM * DD];
__device__ __nv_bfloat16 g_Alo[MM * DD];
__device__ __nv_bfloat16 g_Whi[4 * DD * DD];
__device__ __nv_bfloat16 g_Wlo[4 * DD * DD];

// ---------------------------------------------------------------------------
// Helpers
// ---------------------------------------------------------------------------
__device__ __forceinline__ uint32_t smem_u32(const void* p) {
    uint32_t a;
    asm("{ .reg .u64 t; cvta.to.shared.u64 t, %1; cvt.u32.u64 %0, t; }"
        : "=r"(a) : "l"(p));
    return a;
}

#define SWZ(off) ((uint32_t)(off) ^ ((((uint32_t)(off)) >> 3) & 0x70))

__device__ __forceinline__ void cp_async16(uint32_t dst, const void* src) {
    asm volatile("cp.async.cg.shared.global [%0], [%1], 16;"
                 :: "r"(dst), "l"(src) : "memory");
}
__device__ __forceinline__ void cp_commit() {
    asm volatile("cp.async.commit_group;" ::: "memory");
}
template <int N>
__device__ __forceinline__ void cp_wait() {
    asm volatile("cp.async.wait_group %0;" :: "n"(N) : "memory");
}

__device__ __forceinline__ void ldsm_x4(uint32_t* r, uint32_t addr) {
    asm volatile("ldmatrix.sync.aligned.m8n8.x4.shared.b16 {%0,%1,%2,%3}, [%4];"
                 : "=r"(r[0]), "=r"(r[1]), "=r"(r[2]), "=r"(r[3])
                 : "r"(addr));
}

__device__ __forceinline__ void ldsm_x4_t(uint32_t* r, uint32_t addr) {
    asm volatile("ldmatrix.sync.aligned.m8n8.x4.trans.shared.b16 {%0,%1,%2,%3}, [%4];"
                 : "=r"(r[0]), "=r"(r[1]), "=r"(r[2]), "=r"(r[3])
                 : "r"(addr));
}

__device__ __forceinline__ void mma16816(float* d, const uint32_t* a,
                                         const uint32_t* b) {
    asm volatile(
        "mma.sync.aligned.m16n8k16.row.col.f32.bf16.bf16.f32 "
        "{%0,%1,%2,%3}, {%4,%5,%6,%7}, {%8,%9}, {%0,%1,%2,%3};"
        : "+f"(d[0]), "+f"(d[1]), "+f"(d[2]), "+f"(d[3])
        : "r"(a[0]), "r"(a[1]), "r"(a[2]), "r"(a[3]), "r"(b[0]), "r"(b[1]));
}

__device__ __forceinline__ void mma16816h(float* d, const uint32_t* a,
                                          uint32_t b0, uint32_t b1) {
    asm volatile(
        "mma.sync.aligned.m16n8k16.row.col.f32.f16.f16.f32 "
        "{%0,%1,%2,%3}, {%4,%5,%6,%7}, {%8,%9}, {%0,%1,%2,%3};"
        : "+f"(d[0]), "+f"(d[1]), "+f"(d[2]), "+f"(d[3])
        : "r"(a[0]), "r"(a[1]), "r"(a[2]), "r"(a[3]), "r"(b0), "r"(b1));
}

__device__ __forceinline__ float ex2(float x) {
    float y;
    asm("ex2.approx.ftz.f32 %0, %1;" : "=f"(y) : "f"(x));
    return y;
}

__device__ __forceinline__ uint32_t packbf2(float a, float b) {
    __nv_bfloat162 h = __floats2bfloat162_rn(a, b);
    return *reinterpret_cast<uint32_t*>(&h);
}

// ---------------------------------------------------------------------------
// Splits: fp32 -> bf16 hi + bf16 lo(residual)
// ---------------------------------------------------------------------------
__device__ __forceinline__ void split4(float4 v, uint2& ho, uint2& loo) {
    __nv_bfloat162 h0 = __float22bfloat162_rn(make_float2(v.x, v.y));
    __nv_bfloat162 h1 = __float22bfloat162_rn(make_float2(v.z, v.w));
    float2 hf0 = __bfloat1622float2(h0);
    float2 hf1 = __bfloat1622float2(h1);
    __nv_bfloat162 l0 = __float22bfloat162_rn(make_float2(v.x - hf0.x, v.y - hf0.y));
    __nv_bfloat162 l1 = __float22bfloat162_rn(make_float2(v.z - hf1.x, v.w - hf1.y));
    ho.x = *reinterpret_cast<uint32_t*>(&h0);
    ho.y = *reinterpret_cast<uint32_t*>(&h1);
    loo.x = *reinterpret_cast<uint32_t*>(&l0);
    loo.y = *reinterpret_cast<uint32_t*>(&l1);
}

__global__ void __launch_bounds__(256) split_kernel(
    const float4* __restrict__ src, uint2* __restrict__ hi,
    uint2* __restrict__ lo, int n4)
{
    int i = blockIdx.x * blockDim.x + threadIdx.x;
    if (i >= n4) return;
    uint2 h, l;
    split4(src[i], h, l);
    hi[i] = h;
    lo[i] = l;
}

__global__ void __launch_bounds__(256) split_w4(
    const float4* __restrict__ w0, const float4* __restrict__ w1,
    const float4* __restrict__ w2, const float4* __restrict__ w3,
    uint2* __restrict__ hi, uint2* __restrict__ lo, int n4)
{
    int z = blockIdx.y;
    const float4* src = (z == 0) ? w0 : (z == 1) ? w1 : (z == 2) ? w2 : w3;
    int i = blockIdx.x * blockDim.x + threadIdx.x;
    if (i >= n4) return;
    uint2 h, l;
    split4(src[i], h, l);
    hi[(size_t)z * n4 + i] = h;
    lo[(size_t)z * n4 + i] = l;
}

// ---------------------------------------------------------------------------
// Shared GEMM mainloop (bf16 3-term split), 128x128 tile, 8 warps.
// ---------------------------------------------------------------------------
#define ST_BYTES 65536
#define GEMM_SMEM (2 * ST_BYTES)

struct GemmCtx {
    uint32_t sbase;
    int tid, lane, warp, wm, wn, brow, bcol;
};

__device__ __forceinline__ void gemm_mainloop(
    const GemmCtx& g,
    const __nv_bfloat16* __restrict__ Ahi,
    const __nv_bfloat16* __restrict__ Alo,
    const __nv_bfloat16* __restrict__ Whi,
    const __nv_bfloat16* __restrict__ Wlo,
    float acc[4][4][4])
{
    const int ldr = g.tid >> 3;
    const int ldc = g.tid & 7;
    uint32_t ldswz[4];
#pragma unroll
    for (int i = 0; i < 4; ++i)
        ldswz[i] = SWZ((ldr + i * 32) * 128 + ldc * 16);

    auto issue_stage = [&](int kt, int buf) {
        const uint32_t st = g.sbase + buf * ST_BYTES;
        const int k0 = kt * 64;
#pragma unroll
        for (int i = 0; i < 4; ++i) {
            int r = ldr + i * 32;
            size_t offA = (size_t)(g.brow + r) * DD + k0 + ldc * 8;
            size_t offB = (size_t)(g.bcol + r) * DD + k0 + ldc * 8;
            cp_async16(st + 0     + ldswz[i], Ahi + offA);
            cp_async16(st + 16384 + ldswz[i], Alo + offA);
            cp_async16(st + 32768 + ldswz[i], Whi + offB);
            cp_async16(st + 49152 + ldswz[i], Wlo + offB);
        }
        cp_commit();
    };

    const uint32_t aRowPart = (uint32_t)(g.lane & 15) * 128 + ((g.lane >> 4) << 4);
    const uint32_t bRowPart =
        (uint32_t)((g.lane & 7) + ((g.lane >> 4) << 3)) * 128 +
        (((g.lane >> 3) & 1) << 4);
    uint32_t aswz[4], bswz[4];
#pragma unroll
    for (int kf = 0; kf < 4; ++kf) {
        aswz[kf] = SWZ(aRowPart + kf * 32);
        bswz[kf] = SWZ(bRowPart + kf * 32);
    }
    const uint32_t aWarpOff = g.wm * 8192;
    const uint32_t bWarpOff = g.wn * 4096;

    issue_stage(0, 0);

    for (int kt = 0; kt < 16; ++kt) {
        const int buf = kt & 1;
        if (kt < 15) {
            issue_stage(kt + 1, buf ^ 1);
            cp_wait<1>();
        } else {
            cp_wait<0>();
        }
        __syncthreads();

        const uint32_t st = g.sbase + buf * ST_BYTES;
#pragma unroll
        for (int kf = 0; kf < 4; ++kf) {
            uint32_t ah[4][4], al[4][4], bh[4][2], bl[4][2];
#pragma unroll
            for (int mf = 0; mf < 4; ++mf) {
                uint32_t base = st + aWarpOff + mf * 2048 + aswz[kf];
                ldsm_x4(ah[mf], base);
                ldsm_x4(al[mf], base + 16384);
            }
#pragma unroll
            for (int nf2 = 0; nf2 < 2; ++nf2) {
                uint32_t tmp[4];
                uint32_t base = st + 32768 + bWarpOff + nf2 * 2048 + bswz[kf];
                ldsm_x4(tmp, base);
                bh[2 * nf2 + 0][0] = tmp[0]; bh[2 * nf2 + 0][1] = tmp[1];
                bh[2 * nf2 + 1][0] = tmp[2]; bh[2 * nf2 + 1][1] = tmp[3];
                ldsm_x4(tmp, base + 16384);
                bl[2 * nf2 + 0][0] = tmp[0]; bl[2 * nf2 + 0][1] = tmp[1];
                bl[2 * nf2 + 1][0] = tmp[2]; bl[2 * nf2 + 1][1] = tmp[3];
            }
#pragma unroll
            for (int mf = 0; mf < 4; ++mf)
#pragma unroll
                for (int nf = 0; nf < 4; ++nf) {
                    mma16816(acc[mf][nf], ah[mf], bh[nf]);
                    mma16816(acc[mf][nf], ah[mf], bl[nf]);
                    mma16816(acc[mf][nf], al[mf], bh[nf]);
                }
        }
        __syncthreads();
    }
}

// ---------------------------------------------------------------------------
// Fused QKV GEMM: z selects weight slot / bias / fp16 output / scale.
// ---------------------------------------------------------------------------
__global__ void __launch_bounds__(256) gemm_qkv(
    const __nv_bfloat16* __restrict__ Ahi,
    const __nv_bfloat16* __restrict__ Alo,
    const __nv_bfloat16* __restrict__ WhiBase,
    const __nv_bfloat16* __restrict__ WloBase,
    const float* __restrict__ bq, const float* __restrict__ bk,
    const float* __restrict__ bv,
    __half* __restrict__ Qh, __half* __restrict__ Kh, __half* __restrict__ Vh)
{
    extern __shared__ char smem[];
    const int z = blockIdx.z;
    const __nv_bfloat16* Whi = WhiBase + (size_t)z * DD * DD;
    const __nv_bfloat16* Wlo = WloBase + (size_t)z * DD * DD;
    const float* bias = (z == 0) ? bq : (z == 1) ? bk : bv;
    __half* Ch = (z == 0) ? Qh : (z == 1) ? Kh : Vh;
    const float scl = (z == 0) ? QSCALE : 1.0f;

    GemmCtx g;
    g.sbase = smem_u32(smem);
    g.tid = threadIdx.x; g.lane = g.tid & 31; g.warp = g.tid >> 5;
    g.wm = g.warp >> 2; g.wn = g.warp & 3;
    g.brow = blockIdx.y * 128; g.bcol = blockIdx.x * 128;

    float acc[4][4][4];
#pragma unroll
    for (int i = 0; i < 4; ++i)
#pragma unroll
        for (int j = 0; j < 4; ++j)
#pragma unroll
            for (int t = 0; t < 4; ++t) acc[i][j][t] = 0.0f;

    gemm_mainloop(g, Ahi, Alo, Whi, Wlo, acc);

    const int r0 = g.brow + g.wm * 64 + (g.lane >> 2);
    const int c0 = g.bcol + g.wn * 32 + 2 * (g.lane & 3);
#pragma unroll
    for (int mf = 0; mf < 4; ++mf) {
#pragma unroll
        for (int nf = 0; nf < 4; ++nf) {
            int col = c0 + nf * 8;
            float b0 = bias[col], b1 = bias[col + 1];
            int ra = r0 + mf * 16;
            __half2 o0 = __floats2half2_rn((acc[mf][nf][0] + b0) * scl,
                                           (acc[mf][nf][1] + b1) * scl);
            __half2 o1 = __floats2half2_rn((acc[mf][nf][2] + b0) * scl,
                                           (acc[mf][nf][3] + b1) * scl);
            *reinterpret_cast<__half2*>(&Ch[(size_t)ra * DD + col]) = o0;
            *reinterpret_cast<__half2*>(&Ch[(size_t)(ra + 8) * DD + col]) = o1;
        }
    }
}

// ---------------------------------------------------------------------------
// Output-projection GEMM: fp32 out + bias.
// ---------------------------------------------------------------------------
__global__ void __launch_bounds__(256) gemm_p(
    const __nv_bfloat16* __restrict__ Ahi,
    const __nv_bfloat16* __restrict__ Alo,
    const __nv_bfloat16* __restrict__ Whi,
    const __nv_bfloat16* __restrict__ Wlo,
    const float* __restrict__ bias,
    float* __restrict__ C)
{
    extern __shared__ char smem[];
    GemmCtx g;
    g.sbase = smem_u32(smem);
    g.tid = threadIdx.x; g.lane = g.tid & 31; g.warp = g.tid >> 5;
    g.wm = g.warp >> 2; g.wn = g.warp & 3;
    g.brow = blockIdx.y * 128; g.bcol = blockIdx.x * 128;

    float acc[4][4][4];
#pragma unroll
    for (int i = 0; i < 4; ++i)
#pragma unroll
        for (int j = 0; j < 4; ++j)
#pragma unroll
            for (int t = 0; t < 4; ++t) acc[i][j][t] = 0.0f;

    gemm_mainloop(g, Ahi, Alo, Whi, Wlo, acc);

    const int r0 = g.brow + g.wm * 64 + (g.lane >> 2);
    const int c0 = g.bcol + g.wn * 32 + 2 * (g.lane & 3);
#pragma unroll
    for (int mf = 0; mf < 4; ++mf) {
#pragma unroll
        for (int nf = 0; nf < 4; ++nf) {
            int col = c0 + nf * 8;
            float b0 = bias[col], b1 = bias[col + 1];
            int ra = r0 + mf * 16;
            float2 o0 = make_float2(acc[mf][nf][0] + b0, acc[mf][nf][1] + b1);
            float2 o1 = make_float2(acc[mf][nf][2] + b0, acc[mf][nf][3] + b1);
            *reinterpret_cast<float2*>(&C[(size_t)ra * DD + col]) = o0;
            *reinterpret_cast<float2*>(&C[(size_t)(ra + 8) * DD + col]) = o1;
        }
    }
}

// ---------------------------------------------------------------------------
// Tensor-core flash attention, fp16 in, bf16 hi/lo split out.
// Grid: (NQT/2, H, B); each block does q-tiles {qa, 31-qa} (33 key-tiles).
// __launch_bounds__(128, 4): force <=128 regs -> 4 blocks/SM -> single wave.
// ---------------------------------------------------------------------------
__global__ void __launch_bounds__(128, 4) attn_mma(
    const __half* __restrict__ Qh,
    const __half* __restrict__ Kh,
    const __half* __restrict__ Vh,
    __nv_bfloat16* __restrict__ Yhi,
    __nv_bfloat16* __restrict__ Ylo)
{
    __shared__ char sm[32768];            // 2 bufs x (K 8KB + V 8KB)
    const uint32_t sb = smem_u32(sm);

    const int b    = blockIdx.z;
    const int h    = blockIdx.y;
    const int qa   = blockIdx.x;
    const int tid  = threadIdx.x;
    const int lane = tid & 31;
    const int warp = tid >> 5;
    const int bS   = b * SS;

    // ldmatrix offsets
    const uint32_t bRowPart =
        (uint32_t)((lane & 7) + ((lane >> 4) << 3)) * 128 + (((lane >> 3) & 1) << 4);
    uint32_t kswz[4];
#pragma unroll
    for (int kk = 0; kk < 4; ++kk)
        kswz[kk] = SWZ(bRowPart + kk * 32);
    const uint32_t vRowPart = (uint32_t)(lane & 15) * 128 + ((lane >> 4) << 4);
    uint32_t vswz[4];
#pragma unroll
    for (int nf2 = 0; nf2 < 4; ++nf2)
        vswz[nf2] = SWZ(vRowPart + nf2 * 32);

    // cp.async chunk indexing
    const int ck  = tid >> 3;
    const int ccb = (tid & 7) * 16;
    uint32_t lsw[4];
#pragma unroll
    for (int i = 0; i < 4; ++i)
        lsw[i] = SWZ((ck + i * 16) * 128 + ccb);

    auto issue_tile = [&](int kt, int buf) {
        uint32_t kb = sb + buf * 16384;
        uint32_t vb = kb + 8192;
#pragma unroll
        for (int i = 0; i < 4; ++i) {
            int key = ck + i * 16;
            size_t off = ((size_t)(bS + kt * 64 + key) * DD + h * HD) * 2 + ccb;
            cp_async16(kb + lsw[i], reinterpret_cast<const char*>(Kh) + off);
            cp_async16(vb + lsw[i], reinterpret_cast<const char*>(Vh) + off);
        }
        cp_commit();
    };

#pragma unroll 1
    for (int pass = 0; pass < 2; ++pass) {
        const int qt = pass ? (NQT - 1 - qa) : qa;
        const int row0 = qt * 64 + warp * 16 + (lane >> 2);
        const int row1 = row0 + 8;
        __syncthreads();   // protect smem reuse across passes

        // Q fragments (fp16 global, already scaled)
        uint32_t aq[4][4];
        {
            const __half* qp0 = Qh + (size_t)(bS + row0) * DD + h * HD;
            const __half* qp1 = qp0 + 8 * DD;
#pragma unroll
            for (int kk = 0; kk < 4; ++kk) {
                int k0 = kk * 16 + 2 * (lane & 3);
                aq[kk][0] = *reinterpret_cast<const uint32_t*>(qp0 + k0);
                aq[kk][1] = *reinterpret_cast<const uint32_t*>(qp1 + k0);
                aq[kk][2] = *reinterpret_cast<const uint32_t*>(qp0 + k0 + 8);
                aq[kk][3] = *reinterpret_cast<const uint32_t*>(qp1 + k0 + 8);
            }
        }

        float oacc[8][4];
#pragma unroll
        for (int j = 0; j < 8; ++j)
#pragma unroll
            for (int t = 0; t < 4; ++t) oacc[j][t] = 0.0f;
        float m0 = -1e30f, m1 = -1e30f, l0 = 0.0f, l1 = 0.0f;

        issue_tile(0, 0);

#pragma unroll 1
        for (int kt = 0; kt <= qt; ++kt) {
            const int buf = kt & 1;
            if (kt < qt) {
                issue_tile(kt + 1, buf ^ 1);
                cp_wait<1>();
            } else {
                cp_wait<0>();
            }
            __syncthreads();

            const uint32_t kb = sb + buf * 16384;
            const uint32_t vb = kb + 8192;

            // ---- S = Q K^T (log2 domain) ----
            float sacc[8][4];
#pragma unroll
            for (int j = 0; j < 8; ++j)
#pragma unroll
                for (int t = 0; t < 4; ++t) sacc[j][t] = 0.0f;
#pragma unroll
            for (int kk = 0; kk < 4; ++kk) {
#pragma unroll
                for (int nf2 = 0; nf2 < 4; ++nf2) {
                    uint32_t tmp[4];
                    ldsm_x4(tmp, kb + nf2 * 2048 + kswz[kk]);
                    mma16816h(sacc[2 * nf2 + 0], aq[kk], tmp[0], tmp[1]);
                    mma16816h(sacc[2 * nf2 + 1], aq[kk], tmp[2], tmp[3]);
                }
            }

            if (kt == qt) {
#pragma unroll
                for (int j = 0; j < 8; ++j) {
                    int c = kt * 64 + j * 8 + 2 * (lane & 3);
                    if (c     > row0) sacc[j][0] = -1e30f;
                    if (c + 1 > row0) sacc[j][1] = -1e30f;
                    if (c     > row1) sacc[j][2] = -1e30f;
                    if (c + 1 > row1) sacc[j][3] = -1e30f;
                }
            }

            // ---- online softmax (max + rescale) ----
            float mt0 = sacc[0][0], mt1 = sacc[0][2];
#pragma unroll
            for (int j = 0; j < 8; ++j) {
                mt0 = fmaxf(mt0, fmaxf(sacc[j][0], sacc[j][1]));
                mt1 = fmaxf(mt1, fmaxf(sacc[j][2], sacc[j][3]));
            }
            mt0 = fmaxf(mt0, __shfl_xor_sync(0xffffffffu, mt0, 1));
            mt0 = fmaxf(mt0, __shfl_xor_sync(0xffffffffu, mt0, 2));
            mt1 = fmaxf(mt1, __shfl_xor_sync(0xffffffffu, mt1, 1));
            mt1 = fmaxf(mt1, __shfl_xor_sync(0xffffffffu, mt1, 2));

            float mn0 = fmaxf(m0, mt0);
            float mn1 = fmaxf(m1, mt1);
            float corr0 = ex2(m0 - mn0);
            float corr1 = ex2(m1 - mn1);
            m0 = mn0; m1 = mn1;
            l0 *= corr0; l1 *= corr1;
#pragma unroll
            for (int j = 0; j < 8; ++j) {
                oacc[j][0] *= corr0; oacc[j][1] *= corr0;
                oacc[j][2] *= corr1; oacc[j][3] *= corr1;
            }

            // ---- fused p-compute + O += P V (per kk-step; low reg pressure) ----
#pragma unroll
            for (int kk = 0; kk < 4; ++kk) {
                uint32_t ap[4];
#pragma unroll
                for (int jj = 0; jj < 2; ++jj) {
                    int j = 2 * kk + jj;
                    float p00 = ex2(sacc[j][0] - m0);
                    float p01 = ex2(sacc[j][1] - m0);
                    float p10 = ex2(sacc[j][2] - m1);
                    float p11 = ex2(sacc[j][3] - m1);
                    l0 += p00 + p01;
                    l1 += p10 + p11;
                    __half2 h0 = __floats2half2_rn(p00, p01);
                    __half2 h1 = __floats2half2_rn(p10, p11);
                    ap[2 * jj + 0] = *reinterpret_cast<uint32_t*>(&h0);
                    ap[2 * jj + 1] = *reinterpret_cast<uint32_t*>(&h1);
                }
#pragma unroll
                for (int nf2 = 0; nf2 < 4; ++nf2) {
                    uint32_t tmp[4];
                    ldsm_x4_t(tmp, vb + kk * 2048 + vswz[nf2]);
                    mma16816h(oacc[2 * nf2 + 0], ap, tmp[0], tmp[1]);
                    mma16816h(oacc[2 * nf2 + 1], ap, tmp[2], tmp[3]);
                }
            }
            __syncthreads();
        }

        // ---- finalize: write Y as bf16 hi/lo split ----
        l0 += __shfl_xor_sync(0xffffffffu, l0, 1);
        l0 += __shfl_xor_sync(0xffffffffu, l0, 2);
        l1 += __shfl_xor_sync(0xffffffffu, l1, 1);
        l1 += __shfl_xor_sync(0xffffffffu, l1, 2);
        const float inv0 = 1.0f / l0;
        const float inv1 = 1.0f / l1;

        size_t o0 = (size_t)(bS + row0) * DD + h * HD;
        size_t o1 = (size_t)(bS + row1) * DD + h * HD;
#pragma unroll
        for (int j = 0; j < 8; ++j) {
            int col = j * 8 + 2 * (lane & 3);
            float y00 = oacc[j][0] * inv0, y01 = oacc[j][1] * inv0;
            float y10 = oacc[j][2] * inv1, y11 = oacc[j][3] * inv1;
            float h00 = __bfloat162float(__float2bfloat16_rn(y00));
            float h01 = __bfloat162float(__float2bfloat16_rn(y01));
            float h10 = __bfloat162float(__float2bfloat16_rn(y10));
            float h11 = __bfloat162float(__float2bfloat16_rn(y11));
            *reinterpret_cast<uint32_t*>(&Yhi[o0 + col]) = packbf2(y00, y01);
            *reinterpret_cast<uint32_t*>(&Yhi[o1 + col]) = packbf2(y10, y11);
            *reinterpret_cast<uint32_t*>(&Ylo[o0 + col]) =
                packbf2(y00 - h00, y01 - h01);
            *reinterpret_cast<uint32_t*>(&Ylo[o1 + col]) =
                packbf2(y10 - h10, y11 - h11);
        }
    }
}

// ---------------------------------------------------------------------------
// Launch
// ---------------------------------------------------------------------------
extern "C" void kernel_launch(void* const* d_in, const int* in_sizes, int n_in,
                              void* d_out, int out_size)
{
    (void)in_sizes; (void)n_in; (void)out_size;
    const float* x  = (const float*)d_in[0];
    const float* Wq = (const float*)d_in[1];
    const float* bq = (const float*)d_in[2];
    const float* Wk = (const float*)d_in[3];
    const float* bk = (const float*)d_in[4];
    const float* Wv = (const float*)d_in[5];
    const float* bv = (const float*)d_in[6];
    const float* Wp = (const float*)d_in[7];
    const float* bp = (const float*)d_in[8];
    float* out = (float*)d_out;

    __half *Qh, *Kh, *Vh;
    __nv_bfloat16 *Ahi, *Alo, *Whi, *Wlo;
    cudaGetSymbolAddress((void**)&Qh, g_Qh);
    cudaGetSymbolAddress((void**)&Kh, g_Kh);
    cudaGetSymbolAddress((void**)&Vh, g_Vh);
    cudaGetSymbolAddress((void**)&Ahi, g_Ahi);
    cudaGetSymbolAddress((void**)&Alo, g_Alo);
    cudaGetSymbolAddress((void**)&Whi, g_Whi);
    cudaGetSymbolAddress((void**)&Wlo, g_Wlo);

    cudaFuncSetAttribute(gemm_qkv,
                         cudaFuncAttributeMaxDynamicSharedMemorySize, GEMM_SMEM);
    cudaFuncSetAttribute(gemm_p,
                         cudaFuncAttributeMaxDynamicSharedMemorySize, GEMM_SMEM);

    const int nX4 = MM * DD / 4;
    const int nW4 = DD * DD / 4;

    split_kernel<<<(nX4 + 255) / 256, 256>>>(
        (const float4*)x, (uint2*)Ahi, (uint2*)Alo, nX4);
    split_w4<<<dim3((nW4 + 255) / 256, 4), 256>>>(
        (const float4*)Wq, (const float4*)Wk, (const float4*)Wv,
        (const float4*)Wp, (uint2*)Whi, (uint2*)Wlo, nW4);

    gemm_qkv<<<dim3(DD / 128, MM / 128, 3), 256, GEMM_SMEM>>>(
        Ahi, Alo, Whi, Wlo, bq, bk, bv, Qh, Kh, Vh);

    attn_mma<<<dim3(NQT / 2, HH, BB), 128>>>(Qh, Kh, Vh, Ahi, Alo);

    gemm_p<<<dim3(DD / 128, MM / 128), 256, GEMM_SMEM>>>(
        Ahi, Alo, Whi + (size_t)3 * DD * DD, Wlo + (size_t)3 * DD * DD,
        bp, out);
}